// round 10
// baseline (speedup 1.0000x reference)
#include <cuda_runtime.h>
#include <cuda_bf16.h>
#include <cstdint>

#define BB 8
#define NN 4096
#define SS 1024
#define KNB 16
#define MROWS (BB*SS*KNB)      /* 131072 */
#define XLD 72                 /* 67 cols + 5 zero pad */
#define HLD 136                /* 134 cols + 2 pad */
#define CO  128

// ---------------- device scratch ----------------
__device__ float g_X [(size_t)MROWS * XLD];
__device__ float g_H1[(size_t)MROWS * HLD];
__device__ float g_H2[(size_t)MROWS * HLD];
__device__ float g_H3[(size_t)MROWS * CO];
__device__ float g_SC[(size_t)MROWS * CO];
__device__ int   g_knn[(size_t)MROWS];
__device__ float g_sum[4][160];
__device__ float g_sq [4][160];
__device__ float g_scale[4][160];   // zero-init: pad cols stay 0 forever
__device__ float g_shift[4][160];

// ---------------- zero stats ----------------
__global__ void zero_stats_kernel() {
    int i = threadIdx.x;
    if (i < 640) {
        (&g_sum[0][0])[i] = 0.f;
        (&g_sq [0][0])[i] = 0.f;
    }
}

// ---------------- FPS: one block per batch ----------------
// Exact XLA fp32 arithmetic (no FMA contraction), first-index argmax.
__global__ void fps_kernel(const float* __restrict__ xyz, float* __restrict__ out) {
    extern __shared__ float sm[];
    float* sx = sm;
    float* sy = sm + NN;
    float* sz = sm + 2 * NN;
    __shared__ unsigned long long red[32];
    __shared__ int s_far;

    int b = blockIdx.x;
    int t = threadIdx.x;
    const float* base = xyz + (size_t)b * NN * 3;

    float px[4], py[4], pz[4], pd[4];
#pragma unroll
    for (int i = 0; i < 4; i++) {
        int n = t + i * 1024;
        float x = base[n * 3 + 0], y = base[n * 3 + 1], z = base[n * 3 + 2];
        px[i] = x; py[i] = y; pz[i] = z; pd[i] = 1e10f;
        sx[n] = x; sy[n] = y; sz[n] = z;
    }
    __syncthreads();

    int far = 0;
    for (int s = 0; s < SS; s++) {
        float cx = sx[far], cy = sy[far], cz = sz[far];
        if (t == 0) {
            float* o = out + ((size_t)b * SS + s) * 3;
            o[0] = cx; o[1] = cy; o[2] = cz;
        }
        if (s == SS - 1) break;

        float bv = -1.0f; int bi = 0;
#pragma unroll
        for (int i = 0; i < 4; i++) {
            float dx = __fsub_rn(px[i], cx);
            float dy = __fsub_rn(py[i], cy);
            float dz = __fsub_rn(pz[i], cz);
            float dd = __fadd_rn(__fadd_rn(__fmul_rn(dx, dx), __fmul_rn(dy, dy)),
                                 __fmul_rn(dz, dz));
            float nd = fminf(pd[i], dd);
            pd[i] = nd;
            if (nd > bv) { bv = nd; bi = t + i * 1024; }  // ascending idx: keeps first max
        }
        // max over value; tie -> min index (pack idx as NN - bi)
        unsigned long long key =
            ((unsigned long long)__float_as_uint(bv) << 32) | (unsigned)(NN - bi);
#pragma unroll
        for (int off = 16; off; off >>= 1) {
            unsigned long long o = __shfl_down_sync(0xffffffffu, key, off);
            if (o > key) key = o;
        }
        if ((t & 31) == 0) red[t >> 5] = key;
        __syncthreads();
        if (t < 32) {
            unsigned long long k2 = red[t];
#pragma unroll
            for (int off = 16; off; off >>= 1) {
                unsigned long long o = __shfl_down_sync(0xffffffffu, k2, off);
                if (o > k2) k2 = o;
            }
            if (t == 0) s_far = NN - (int)(k2 & 0xffffffffu);
        }
        __syncthreads();
        far = s_far;
    }
}

// ---------------- kNN: 16 smallest of 4096, set semantics ----------------
__global__ void knn_kernel(const float* __restrict__ xyz,
                           const float* __restrict__ newxyz) {
    extern __shared__ unsigned char smraw[];
    float4* tile = (float4*)smraw;                 // 4096 float4
    float*  sdist = (float*)(tile + NN);           // [16][128]
    int*    sidx  = (int*)(sdist + 16 * 128);      // [16][128]

    int b = blockIdx.y;
    int t = threadIdx.x;
    const float* base = xyz + (size_t)b * NN * 3;
#pragma unroll 4
    for (int i = 0; i < NN / 128; i++) {
        int n = t + i * 128;
        float x = base[n * 3 + 0], y = base[n * 3 + 1], z = base[n * 3 + 2];
        tile[n] = make_float4(x, y, z, 0.5f * (x * x + y * y + z * z));
    }
    int sq = blockIdx.x * 128 + t;
    const float* q = newxyz + ((size_t)b * SS + sq) * 3;
    float qx = q[0], qy = q[1], qz = q[2];
    float qh = 0.5f * (qx * qx + qy * qy + qz * qz);
    float nqx = -qx, nqy = -qy, nqz = -qz;

#pragma unroll
    for (int sl = 0; sl < KNB; sl++) {
        sdist[sl * 128 + t] = 1e30f;
        sidx [sl * 128 + t] = 0;
    }
    __syncthreads();

    float maxv = 1e30f;
    int maxslot = 0;
    for (int j = 0; j < NN; j++) {
        float4 p = tile[j];
        float m = fmaf(nqx, p.x, fmaf(nqy, p.y, fmaf(nqz, p.z, qh + p.w)));
        if (m < maxv) {
            sdist[maxslot * 128 + t] = m;
            sidx [maxslot * 128 + t] = j;
            float mv = -1e30f; int ms = 0;
#pragma unroll
            for (int sl = 0; sl < KNB; sl++) {
                float d = sdist[sl * 128 + t];
                if (d > mv) { mv = d; ms = sl; }
            }
            maxv = mv; maxslot = ms;
        }
    }
    size_t rbase = ((size_t)b * SS + sq) * KNB;
#pragma unroll
    for (int sl = 0; sl < KNB; sl++)
        g_knn[rbase + sl] = sidx[sl * 128 + t];
}

// ---------------- gather: build X[M,72] ----------------
__global__ void gather_kernel(const float* __restrict__ xyz,
                              const float* __restrict__ pts,
                              const float* __restrict__ newxyz) {
    size_t gid = (size_t)blockIdx.x * 256 + threadIdx.x;
    if (gid >= (size_t)MROWS * XLD) return;
    int col = (int)(gid % XLD);
    size_t row = gid / XLD;
    size_t bs = row >> 4;          // b*S + s
    int b = (int)(bs >> 10);
    int n = g_knn[row];
    float v;
    if (col < 3)
        v = xyz[((size_t)b * NN + n) * 3 + col] - newxyz[bs * 3 + col];
    else if (col < 67)
        v = pts[((size_t)b * NN + n) * 64 + (col - 3)];
    else
        v = 0.0f;
    g_X[row * XLD + col] = v;
}

// ---------------- GEMM: 128 rows x full N, weights smem-resident ----------------
// C = act(A) @ W + bias ; act = identity (pscale==null) or relu(a*scale+shift)
__global__ __launch_bounds__(256) void gemm_kernel(
    const float* __restrict__ A, int lda,
    const float* __restrict__ W, int kreal, int nc,
    const float* __restrict__ bias,
    const float* __restrict__ pscale, const float* __restrict__ pshift,
    float* __restrict__ C, int ldc, int ktiles)
{
    extern __shared__ float sm[];
    float* sB    = sm;                 // [<=136][136]
    float* sA    = sB + 136 * 136;     // [8][128]
    float* sBias = sA + 8 * 128;       // [136]
    float* sSc   = sBias + 136;        // [136]
    float* sSh   = sSc + 136;          // [136]

    int t = threadIdx.x;
    int K8 = ktiles * 8;

    for (int i = t; i < K8 * 136; i += 256) {
        int k = i / 136, c = i - k * 136;
        sB[i] = (k < kreal && c < nc) ? W[k * nc + c] : 0.f;
    }
    if (t < 136) {
        sBias[t] = (t < nc) ? bias[t] : 0.f;
        if (pscale) { sSc[t] = pscale[t]; sSh[t] = pshift[t]; }
    }
    // CRITICAL: staging -> first use of sSc/sSh in the iter-0 A-load below.
    // Without this barrier, warps with t>=136 race ahead and read garbage
    // BN scale/shift (the round-8 30% error on output 1).
    __syncthreads();

    int ty = t >> 4, tx = t & 15;
    size_t rowbase = (size_t)blockIdx.x * 128;
    int ar = t >> 1, aq = t & 1;

    float acc[8][9];
#pragma unroll
    for (int r = 0; r < 8; r++)
#pragma unroll
        for (int c = 0; c < 9; c++) acc[r][c] = 0.f;

    for (int kt = 0; kt < ktiles; kt++) {
        float4 v = *(const float4*)(A + (rowbase + ar) * lda + kt * 8 + aq * 4);
        if (pscale) {
            int kb = kt * 8 + aq * 4;
            v.x = fmaxf(fmaf(v.x, sSc[kb + 0], sSh[kb + 0]), 0.f);
            v.y = fmaxf(fmaf(v.y, sSc[kb + 1], sSh[kb + 1]), 0.f);
            v.z = fmaxf(fmaf(v.z, sSc[kb + 2], sSh[kb + 2]), 0.f);
            v.w = fmaxf(fmaf(v.w, sSc[kb + 3], sSh[kb + 3]), 0.f);
        }
        __syncthreads();   // prev tile's sA fully consumed
        sA[(aq * 4 + 0) * 128 + ar] = v.x;
        sA[(aq * 4 + 1) * 128 + ar] = v.y;
        sA[(aq * 4 + 2) * 128 + ar] = v.z;
        sA[(aq * 4 + 3) * 128 + ar] = v.w;
        __syncthreads();

#pragma unroll
        for (int kk = 0; kk < 8; kk++) {
            float a[8], bf[9];
            const float* sak = sA + kk * 128 + ty * 8;
            *(float4*)(a)     = *(const float4*)(sak);
            *(float4*)(a + 4) = *(const float4*)(sak + 4);
            const float* sbk = sB + (kt * 8 + kk) * 136 + tx;
#pragma unroll
            for (int c = 0; c < 9; c++) bf[c] = sbk[c * 16];
#pragma unroll
            for (int r = 0; r < 8; r++)
#pragma unroll
                for (int c = 0; c < 9; c++)
                    acc[r][c] = fmaf(a[r], bf[c], acc[r][c]);
        }
    }

#pragma unroll
    for (int r = 0; r < 8; r++) {
        size_t row = rowbase + ty * 8 + r;
#pragma unroll
        for (int c = 0; c < 9; c++) {
            int col = tx + 16 * c;
            if (col < nc) C[row * ldc + col] = acc[r][c] + sBias[col];
        }
    }
}

// ---------------- column stats (E[x], E[x^2]) ----------------
__global__ void stats_kernel(const float* __restrict__ H, int ld, int nc, int layer) {
    int c = threadIdx.x;
    if (c >= nc) return;
    size_t r0 = (size_t)blockIdx.x * 512;
    float s0 = 0, s1 = 0, q0 = 0, q1 = 0;
#pragma unroll 4
    for (int r = 0; r < 512; r += 2) {
        float v0 = H[(r0 + r) * ld + c];
        float v1 = H[(r0 + r + 1) * ld + c];
        s0 += v0; s1 += v1;
        q0 = fmaf(v0, v0, q0); q1 = fmaf(v1, v1, q1);
    }
    atomicAdd(&g_sum[layer][c], s0 + s1);
    atomicAdd(&g_sq [layer][c], q0 + q1);
}

__global__ void finalize_kernel(const float* __restrict__ gamma,
                                const float* __restrict__ beta, int nc, int layer) {
    int c = threadIdx.x;
    if (c >= nc) return;
    const float inv = 1.0f / (float)MROWS;
    float m = g_sum[layer][c] * inv;
    float v = g_sq[layer][c] * inv - m * m;
    float sc = gamma[c] * rsqrtf(v + 1e-5f);
    g_scale[layer][c] = sc;
    g_shift[layer][c] = beta[c] - m * sc;
}

// ---------------- final: relu(bn3(H3)+bnsc(SC)), max over K ----------------
__global__ void final_kernel(float* __restrict__ out) {
    int c = threadIdx.x;                 // 0..127
    size_t bs = blockIdx.x;              // 0..8191
    float s3 = g_scale[2][c], h3 = g_shift[2][c];
    float ssc = g_scale[3][c], hsc = g_shift[3][c];
    float mx = 0.0f;                     // relu output >= 0
    size_t base = bs * KNB;
#pragma unroll
    for (int kk = 0; kk < KNB; kk++) {
        float a  = fmaf(g_H3[(base + kk) * CO + c], s3, h3);
        float b2 = fmaf(g_SC[(base + kk) * CO + c], ssc, hsc);
        mx = fmaxf(mx, fmaxf(a + b2, 0.f));
    }
    out[24576 + bs * CO + c] = mx;
}

// ---------------- launch ----------------
extern "C" void kernel_launch(void* const* d_in, const int* in_sizes, int n_in,
                              void* d_out, int out_size) {
    const float* xyz   = (const float*)d_in[0];
    const float* pts   = (const float*)d_in[1];
    const float* fc1_w = (const float*)d_in[2];
    const float* fc1_b = (const float*)d_in[3];
    const float* bn1_g = (const float*)d_in[4];
    const float* bn1_b = (const float*)d_in[5];
    const float* fc2_w = (const float*)d_in[6];
    const float* fc2_b = (const float*)d_in[7];
    const float* bn2_g = (const float*)d_in[8];
    const float* bn2_b = (const float*)d_in[9];
    const float* fc3_w = (const float*)d_in[10];
    const float* fc3_b = (const float*)d_in[11];
    const float* bn3_g = (const float*)d_in[12];
    const float* bn3_b = (const float*)d_in[13];
    const float* sc_w  = (const float*)d_in[14];
    const float* sc_b  = (const float*)d_in[15];
    const float* scbn_g = (const float*)d_in[16];
    const float* scbn_b = (const float*)d_in[17];
    float* out = (float*)d_out;

    void *pX, *pH1, *pH2, *pH3, *pSC, *pScale, *pShift;
    cudaGetSymbolAddress(&pX,  g_X);
    cudaGetSymbolAddress(&pH1, g_H1);
    cudaGetSymbolAddress(&pH2, g_H2);
    cudaGetSymbolAddress(&pH3, g_H3);
    cudaGetSymbolAddress(&pSC, g_SC);
    cudaGetSymbolAddress(&pScale, g_scale);
    cudaGetSymbolAddress(&pShift, g_shift);
    float* X  = (float*)pX;
    float* H1 = (float*)pH1;
    float* H2 = (float*)pH2;
    float* H3 = (float*)pH3;
    float* SC = (float*)pSC;
    float* scl = (float*)pScale;   // [4][160]
    float* shf = (float*)pShift;

    const int fps_smem  = 3 * NN * 4;                            // 49152
    const int knn_smem  = NN * 16 + 16 * 128 * 4 * 2;            // 81920
    const int gemm_smem = (136 * 136 + 8 * 128 + 136 * 3) * 4;   // 79712

    cudaFuncSetAttribute(fps_kernel,  cudaFuncAttributeMaxDynamicSharedMemorySize, fps_smem);
    cudaFuncSetAttribute(knn_kernel,  cudaFuncAttributeMaxDynamicSharedMemorySize, knn_smem);
    cudaFuncSetAttribute(gemm_kernel, cudaFuncAttributeMaxDynamicSharedMemorySize, gemm_smem);

    zero_stats_kernel<<<1, 1024>>>();
    fps_kernel<<<BB, 1024, fps_smem>>>(xyz, out);
    knn_kernel<<<dim3(SS / 128, BB), 128, knn_smem>>>(xyz, out);
    {
        size_t tot = (size_t)MROWS * XLD;
        gather_kernel<<<(unsigned)((tot + 255) / 256), 256>>>(xyz, pts, out);
    }

    // layer 1: H1 = X @ fc1_w + b            (K=67 pad 72, N=134)
    gemm_kernel<<<MROWS / 128, 256, gemm_smem>>>(X, XLD, fc1_w, 67, 134, fc1_b,
                                                 nullptr, nullptr, H1, HLD, 9);
    stats_kernel<<<256, 160>>>(H1, HLD, 134, 0);
    finalize_kernel<<<1, 160>>>(bn1_g, bn1_b, 134, 0);

    // shortcut: SC = X @ sc_w + b            (K=67, N=128)
    gemm_kernel<<<MROWS / 128, 256, gemm_smem>>>(X, XLD, sc_w, 67, 128, sc_b,
                                                 nullptr, nullptr, SC, CO, 9);
    stats_kernel<<<256, 160>>>(SC, CO, 128, 3);
    finalize_kernel<<<1, 160>>>(scbn_g, scbn_b, 128, 3);

    // layer 2: H2 = relu(bn1(H1)) @ fc2_w + b  (K=134 pad 136, N=134)
    gemm_kernel<<<MROWS / 128, 256, gemm_smem>>>(H1, HLD, fc2_w, 134, 134, fc2_b,
                                                 scl + 0 * 160, shf + 0 * 160, H2, HLD, 17);
    stats_kernel<<<256, 160>>>(H2, HLD, 134, 1);
    finalize_kernel<<<1, 160>>>(bn2_g, bn2_b, 134, 1);

    // layer 3: H3 = relu(bn2(H2)) @ fc3_w + b  (K=134, N=128)
    gemm_kernel<<<MROWS / 128, 256, gemm_smem>>>(H2, HLD, fc3_w, 134, 128, fc3_b,
                                                 scl + 1 * 160, shf + 1 * 160, H3, CO, 17);
    stats_kernel<<<256, 160>>>(H3, CO, 128, 2);
    finalize_kernel<<<1, 160>>>(bn3_g, bn3_b, 128, 2);

    final_kernel<<<BB * SS, 128>>>(out);
}

// round 11
// speedup vs baseline: 1.2575x; 1.2575x over previous
#include <cuda_runtime.h>
#include <cuda_bf16.h>
#include <cstdint>

#define BB 8
#define NN 4096
#define SS 1024
#define KNB 16
#define MROWS (BB*SS*KNB)      /* 131072 */
#define XLD 72                 /* [pts 64 | dxyz 3 | pad 5] */
#define HLD 136                /* 134 cols + 2 pad */
#define CO  128

// ---------------- device scratch ----------------
__device__ float g_X [(size_t)MROWS * XLD];
__device__ float g_H1[(size_t)MROWS * HLD];
__device__ float g_H2[(size_t)MROWS * HLD];
__device__ float g_H3[(size_t)MROWS * CO];
__device__ float g_SC[(size_t)MROWS * CO];
__device__ int   g_knn[(size_t)MROWS];
__device__ float g_sum[4][160];
__device__ float g_sq [4][160];

// ---------------- zero stats ----------------
__global__ void zero_stats_kernel() {
    int i = threadIdx.x;
    if (i < 640) {
        (&g_sum[0][0])[i] = 0.f;
        (&g_sq [0][0])[i] = 0.f;
    }
}

// ---------------- FPS: one block per batch ----------------
// Exact XLA fp32 arithmetic (no FMA contraction), first-index argmax.
// Reduction: redux.max on float bits (valid: all dists >= 0) + redux.min on
// masked index -> exact "first max" semantics with a short dependence chain.
__global__ void fps_kernel(const float* __restrict__ xyz, float* __restrict__ out) {
    extern __shared__ float sm[];
    float* sx = sm;
    float* sy = sm + NN;
    float* sz = sm + 2 * NN;
    __shared__ unsigned redv[32];
    __shared__ unsigned redi[32];

    int b = blockIdx.x;
    int t = threadIdx.x;
    int lane = t & 31, w = t >> 5;
    const float* base = xyz + (size_t)b * NN * 3;

    float px[4], py[4], pz[4], pd[4];
#pragma unroll
    for (int i = 0; i < 4; i++) {
        int n = t + i * 1024;
        float x = base[n * 3 + 0], y = base[n * 3 + 1], z = base[n * 3 + 2];
        px[i] = x; py[i] = y; pz[i] = z; pd[i] = 1e10f;
        sx[n] = x; sy[n] = y; sz[n] = z;
    }
    __syncthreads();

    int far = 0;
    for (int s = 0; s < SS; s++) {
        float cx = sx[far], cy = sy[far], cz = sz[far];
        if (t == 0) {
            float* o = out + ((size_t)b * SS + s) * 3;
            o[0] = cx; o[1] = cy; o[2] = cz;
        }
        if (s == SS - 1) break;

        float bv = -1.0f; int bi = 0;
#pragma unroll
        for (int i = 0; i < 4; i++) {
            float dx = __fsub_rn(px[i], cx);
            float dy = __fsub_rn(py[i], cy);
            float dz = __fsub_rn(pz[i], cz);
            float dd = __fadd_rn(__fadd_rn(__fmul_rn(dx, dx), __fmul_rn(dy, dy)),
                                 __fmul_rn(dz, dz));
            float nd = fminf(pd[i], dd);
            pd[i] = nd;
            if (nd > bv) { bv = nd; bi = t + i * 1024; }  // ascending idx: first max kept
        }
        // stage 1: warp max value, min index among ties
        unsigned vb = __float_as_uint(bv);               // bv >= 0 -> order-preserving
        unsigned mx = __reduce_max_sync(0xffffffffu, vb);
        unsigned cand = (vb == mx) ? (unsigned)bi : 0xffffffffu;
        unsigned mi = __reduce_min_sync(0xffffffffu, cand);

        __syncthreads();                 // prev iter's stage-2 readers done
        if (lane == 0) { redv[w] = mx; redi[w] = mi; }
        __syncthreads();

        // stage 2: all warps redundantly (no broadcast hop)
        unsigned v2 = redv[lane], i2 = redi[lane];
        unsigned m2 = __reduce_max_sync(0xffffffffu, v2);
        unsigned c2 = (v2 == m2) ? i2 : 0xffffffffu;
        far = (int)__reduce_min_sync(0xffffffffu, c2);
    }
}

// ---------------- kNN: 16 smallest of 4096, set semantics ----------------
__global__ void knn_kernel(const float* __restrict__ xyz,
                           const float* __restrict__ newxyz) {
    extern __shared__ unsigned char smraw[];
    float4* tile = (float4*)smraw;                 // 4096 float4
    float*  sdist = (float*)(tile + NN);           // [16][128]
    int*    sidx  = (int*)(sdist + 16 * 128);      // [16][128]

    int b = blockIdx.y;
    int t = threadIdx.x;
    const float* base = xyz + (size_t)b * NN * 3;
#pragma unroll 4
    for (int i = 0; i < NN / 128; i++) {
        int n = t + i * 128;
        float x = base[n * 3 + 0], y = base[n * 3 + 1], z = base[n * 3 + 2];
        tile[n] = make_float4(x, y, z, 0.5f * (x * x + y * y + z * z));
    }
    int sq = blockIdx.x * 128 + t;
    const float* q = newxyz + ((size_t)b * SS + sq) * 3;
    float qx = q[0], qy = q[1], qz = q[2];
    float qh = 0.5f * (qx * qx + qy * qy + qz * qz);
    float nqx = -qx, nqy = -qy, nqz = -qz;

#pragma unroll
    for (int sl = 0; sl < KNB; sl++) {
        sdist[sl * 128 + t] = 1e30f;
        sidx [sl * 128 + t] = 0;
    }
    __syncthreads();

    float maxv = 1e30f;
    int maxslot = 0;
    for (int j = 0; j < NN; j++) {
        float4 p = tile[j];
        float m = fmaf(nqx, p.x, fmaf(nqy, p.y, fmaf(nqz, p.z, qh + p.w)));
        if (m < maxv) {
            sdist[maxslot * 128 + t] = m;
            sidx [maxslot * 128 + t] = j;
            float mv = -1e30f; int ms = 0;
#pragma unroll
            for (int sl = 0; sl < KNB; sl++) {
                float d = sdist[sl * 128 + t];
                if (d > mv) { mv = d; ms = sl; }
            }
            maxv = mv; maxslot = ms;
        }
    }
    size_t rbase = ((size_t)b * SS + sq) * KNB;
#pragma unroll
    for (int sl = 0; sl < KNB; sl++)
        g_knn[rbase + sl] = sidx[sl * 128 + t];
}

// ---------------- gather: build X[M,72] = [pts 64 | dxyz 3 | pad 5], float4 ----------------
__global__ void gather_kernel(const float* __restrict__ xyz,
                              const float* __restrict__ pts,
                              const float* __restrict__ newxyz) {
    size_t gid = (size_t)blockIdx.x * 256 + threadIdx.x;   // row*18 + c4
    if (gid >= (size_t)MROWS * 18) return;
    int c4 = (int)(gid % 18);
    size_t row = gid / 18;
    size_t bs = row >> 4;          // b*S + s
    int b = (int)(bs >> 10);
    int n = g_knn[row];
    float4 v;
    if (c4 < 16) {
        v = ((const float4*)(pts + ((size_t)b * NN + n) * 64))[c4];
    } else if (c4 == 16) {
        const float* p = xyz + ((size_t)b * NN + n) * 3;
        const float* q = newxyz + bs * 3;
        v = make_float4(p[0] - q[0], p[1] - q[1], p[2] - q[2], 0.f);
    } else {
        v = make_float4(0.f, 0.f, 0.f, 0.f);
    }
    ((float4*)(g_X + row * XLD))[c4] = v;
}

// ---------------- GEMM: 128 rows x full N, weights smem-resident ----------------
// C = act(A) @ W + bias.  USEBN: act = relu(a*scale+shift) with scale/shift
// computed in-block from g_sum/g_sq[inlayer] + gamma/beta.
// Epilogue: fused column stats (sum, sumsq) -> atomicAdd into g_sum/g_sq[outlayer].
// perm: remap W rows for the [pts|dxyz] X layout (k<64 -> k+3, else k-64).
template<bool USEBN>
__global__ __launch_bounds__(256) void gemm_kernel(
    const float* __restrict__ A, int lda,
    const float* __restrict__ W, int kreal, int nc, int perm,
    const float* __restrict__ bias,
    const float* __restrict__ gamma, const float* __restrict__ beta,
    int inlayer, int ncin,
    float* __restrict__ C, int ldc, int ktiles, int outlayer)
{
    extern __shared__ float sm[];
    float* sB    = sm;                 // [K8<=136][136]; reused as stats scratch
    float* sA    = sB + 136 * 136;     // [8][128]
    float* sBias = sA + 8 * 128;       // [144]
    float* sSc   = sBias + 144;        // [136]
    float* sSh   = sSc + 136;          // [136]

    int t = threadIdx.x;
    int K8 = ktiles * 8;

    for (int i = t; i < K8 * 136; i += 256) {
        int k = i / 136, c = i - k * 136;
        float wv = 0.f;
        if (k < kreal && c < nc) {
            int kk = perm ? (k < 64 ? k + 3 : k - 64) : k;
            wv = W[kk * nc + c];
        }
        sB[i] = wv;
    }
    if (t < 144) sBias[t] = (t < nc) ? bias[t] : 0.f;
    if (USEBN && t < 136) {
        float scv = 0.f, shv = 0.f;
        if (t < ncin) {
            const float inv = 1.0f / (float)MROWS;
            float m = g_sum[inlayer][t] * inv;
            float v = g_sq [inlayer][t] * inv - m * m;
            scv = gamma[t] * rsqrtf(v + 1e-5f);
            shv = beta[t] - m * scv;
        }
        sSc[t] = scv; sSh[t] = shv;
    }
    __syncthreads();

    int ty = t >> 4, tx = t & 15;
    size_t rowbase = (size_t)blockIdx.x * 128;
    int ar = t >> 1, aq = t & 1;

    float acc[8][9];
#pragma unroll
    for (int r = 0; r < 8; r++)
#pragma unroll
        for (int c = 0; c < 9; c++) acc[r][c] = 0.f;

    for (int kt = 0; kt < ktiles; kt++) {
        float4 v = *(const float4*)(A + (rowbase + ar) * lda + kt * 8 + aq * 4);
        if (USEBN) {
            int kb = kt * 8 + aq * 4;
            v.x = fmaxf(fmaf(v.x, sSc[kb + 0], sSh[kb + 0]), 0.f);
            v.y = fmaxf(fmaf(v.y, sSc[kb + 1], sSh[kb + 1]), 0.f);
            v.z = fmaxf(fmaf(v.z, sSc[kb + 2], sSh[kb + 2]), 0.f);
            v.w = fmaxf(fmaf(v.w, sSc[kb + 3], sSh[kb + 3]), 0.f);
        }
        __syncthreads();   // prev tile's sA fully consumed
        sA[(aq * 4 + 0) * 128 + ar] = v.x;
        sA[(aq * 4 + 1) * 128 + ar] = v.y;
        sA[(aq * 4 + 2) * 128 + ar] = v.z;
        sA[(aq * 4 + 3) * 128 + ar] = v.w;
        __syncthreads();

#pragma unroll
        for (int kk = 0; kk < 8; kk++) {
            float a[8], bf[9];
            const float* sak = sA + kk * 128 + ty * 8;
            *(float4*)(a)     = *(const float4*)(sak);
            *(float4*)(a + 4) = *(const float4*)(sak + 4);
            const float* sbk = sB + (kt * 8 + kk) * 136 + tx;
#pragma unroll
            for (int c = 0; c < 9; c++) bf[c] = sbk[c * 16];
#pragma unroll
            for (int r = 0; r < 8; r++)
#pragma unroll
                for (int c = 0; c < 9; c++)
                    acc[r][c] = fmaf(a[r], bf[c], acc[r][c]);
        }
    }

    // epilogue: store + per-thread column partial stats
    float s_[9], q_[9];
#pragma unroll
    for (int c = 0; c < 9; c++) { s_[c] = 0.f; q_[c] = 0.f; }
#pragma unroll
    for (int r = 0; r < 8; r++) {
        size_t row = rowbase + ty * 8 + r;
#pragma unroll
        for (int c = 0; c < 9; c++) {
            int col = tx + 16 * c;
            float val = acc[r][c] + sBias[col];
            s_[c] += val;
            q_[c] = fmaf(val, val, q_[c]);
            if (col < nc) C[row * ldc + col] = val;
        }
    }
    __syncthreads();                       // all warps done reading sB
#pragma unroll
    for (int c = 0; c < 9; c++) {
        int col = tx + 16 * c;
        sB[ty * 144 + col]        = s_[c];
        sB[2304 + ty * 144 + col] = q_[c];
    }
    __syncthreads();
    if (t < 144) {
        float s = 0.f, q = 0.f;
#pragma unroll
        for (int y = 0; y < 16; y++) {
            s += sB[y * 144 + t];
            q += sB[2304 + y * 144 + t];
        }
        atomicAdd(&g_sum[outlayer][t], s);
        atomicAdd(&g_sq [outlayer][t], q);
    }
}

// ---------------- final: relu(bn3(H3)+bnsc(SC)), max over K ----------------
__global__ void final_kernel(const float* __restrict__ g3, const float* __restrict__ b3,
                             const float* __restrict__ gsc, const float* __restrict__ bsc,
                             float* __restrict__ out) {
    int c = threadIdx.x;                 // 0..127
    size_t bs = blockIdx.x;              // 0..8191
    const float inv = 1.0f / (float)MROWS;
    float m = g_sum[2][c] * inv;
    float v = g_sq[2][c] * inv - m * m;
    float s3 = g3[c] * rsqrtf(v + 1e-5f);
    float h3 = b3[c] - m * s3;
    m = g_sum[3][c] * inv;
    v = g_sq[3][c] * inv - m * m;
    float ssc = gsc[c] * rsqrtf(v + 1e-5f);
    float hsc = bsc[c] - m * ssc;

    float mx = 0.0f;                     // relu output >= 0
    size_t base = bs * KNB;
#pragma unroll
    for (int kk = 0; kk < KNB; kk++) {
        float a  = fmaf(g_H3[(base + kk) * CO + c], s3, h3);
        float b2 = fmaf(g_SC[(base + kk) * CO + c], ssc, hsc);
        mx = fmaxf(mx, fmaxf(a + b2, 0.f));
    }
    out[24576 + bs * CO + c] = mx;
}

// ---------------- launch ----------------
extern "C" void kernel_launch(void* const* d_in, const int* in_sizes, int n_in,
                              void* d_out, int out_size) {
    const float* xyz   = (const float*)d_in[0];
    const float* pts   = (const float*)d_in[1];
    const float* fc1_w = (const float*)d_in[2];
    const float* fc1_b = (const float*)d_in[3];
    const float* bn1_g = (const float*)d_in[4];
    const float* bn1_b = (const float*)d_in[5];
    const float* fc2_w = (const float*)d_in[6];
    const float* fc2_b = (const float*)d_in[7];
    const float* bn2_g = (const float*)d_in[8];
    const float* bn2_b = (const float*)d_in[9];
    const float* fc3_w = (const float*)d_in[10];
    const float* fc3_b = (const float*)d_in[11];
    const float* bn3_g = (const float*)d_in[12];
    const float* bn3_b = (const float*)d_in[13];
    const float* sc_w  = (const float*)d_in[14];
    const float* sc_b  = (const float*)d_in[15];
    const float* scbn_g = (const float*)d_in[16];
    const float* scbn_b = (const float*)d_in[17];
    float* out = (float*)d_out;

    void *pX, *pH1, *pH2, *pH3, *pSC;
    cudaGetSymbolAddress(&pX,  g_X);
    cudaGetSymbolAddress(&pH1, g_H1);
    cudaGetSymbolAddress(&pH2, g_H2);
    cudaGetSymbolAddress(&pH3, g_H3);
    cudaGetSymbolAddress(&pSC, g_SC);
    float* X  = (float*)pX;
    float* H1 = (float*)pH1;
    float* H2 = (float*)pH2;
    float* H3 = (float*)pH3;
    float* SC = (float*)pSC;

    const int fps_smem  = 3 * NN * 4;                              // 49152
    const int knn_smem  = NN * 16 + 16 * 128 * 4 * 2;              // 81920
    const int gemm_smem = (136 * 136 + 8 * 128 + 144 + 136 * 2) * 4; // 79744

    cudaFuncSetAttribute(fps_kernel,  cudaFuncAttributeMaxDynamicSharedMemorySize, fps_smem);
    cudaFuncSetAttribute(knn_kernel,  cudaFuncAttributeMaxDynamicSharedMemorySize, knn_smem);
    cudaFuncSetAttribute(gemm_kernel<false>, cudaFuncAttributeMaxDynamicSharedMemorySize, gemm_smem);
    cudaFuncSetAttribute(gemm_kernel<true>,  cudaFuncAttributeMaxDynamicSharedMemorySize, gemm_smem);

    zero_stats_kernel<<<1, 1024>>>();
    fps_kernel<<<BB, 1024, fps_smem>>>(xyz, out);
    knn_kernel<<<dim3(SS / 128, BB), 128, knn_smem>>>(xyz, out);
    gather_kernel<<<(MROWS * 18) / 256, 256>>>(xyz, pts, out);

    // layer 1: H1 = X @ fc1_w + b            (K=67 perm, N=134) -> stats[0]
    gemm_kernel<false><<<MROWS / 128, 256, gemm_smem>>>(
        X, XLD, fc1_w, 67, 134, 1, fc1_b, nullptr, nullptr, 0, 0, H1, HLD, 9, 0);

    // shortcut: SC = X @ sc_w + b            (K=67 perm, N=128) -> stats[3]
    gemm_kernel<false><<<MROWS / 128, 256, gemm_smem>>>(
        X, XLD, sc_w, 67, 128, 1, sc_b, nullptr, nullptr, 0, 0, SC, CO, 9, 3);

    // layer 2: H2 = relu(bn1(H1)) @ fc2_w + b  (K=134, N=134) -> stats[1]
    gemm_kernel<true><<<MROWS / 128, 256, gemm_smem>>>(
        H1, HLD, fc2_w, 134, 134, 0, fc2_b, bn1_g, bn1_b, 0, 134, H2, HLD, 17, 1);

    // layer 3: H3 = relu(bn2(H2)) @ fc3_w + b  (K=134, N=128) -> stats[2]
    gemm_kernel<true><<<MROWS / 128, 256, gemm_smem>>>(
        H2, HLD, fc3_w, 134, 128, 0, fc3_b, bn2_g, bn2_b, 1, 134, H3, CO, 17, 2);

    final_kernel<<<BB * SS, 128>>>(bn3_g, bn3_b, scbn_g, scbn_b, out);
}

// round 12
// speedup vs baseline: 1.3310x; 1.0585x over previous
#include <cuda_runtime.h>
#include <cuda_bf16.h>
#include <cstdint>

#define BB 8
#define NN 4096
#define SS 1024
#define KNB 16
#define MROWS (BB*SS*KNB)      /* 131072 */
#define XLD 72                 /* [pts 64 | dxyz 3 | pad 5] */
#define HLD 136                /* 134 cols + 2 pad */
#define CO  128

// ---------------- device scratch ----------------
__device__ float g_X [(size_t)MROWS * XLD];
__device__ float g_H1[(size_t)MROWS * HLD];
__device__ float g_H2[(size_t)MROWS * HLD];
__device__ float g_H3[(size_t)MROWS * CO];
__device__ float g_SC[(size_t)MROWS * CO];
__device__ int   g_knn[(size_t)MROWS];
__device__ float g_sum[4][160];
__device__ float g_sq [4][160];

// ---------------- zero stats ----------------
__global__ void zero_stats_kernel() {
    int i = threadIdx.x;
    if (i < 640) {
        (&g_sum[0][0])[i] = 0.f;
        (&g_sq [0][0])[i] = 0.f;
    }
}

// ---------------- packed f32x2 helpers ----------------
__device__ __forceinline__ unsigned long long pack2(float lo, float hi) {
    unsigned long long r;
    asm("mov.b64 %0, {%1, %2};" : "=l"(r) : "r"(__float_as_uint(lo)), "r"(__float_as_uint(hi)));
    return r;
}
__device__ __forceinline__ void unpack2(float& lo, float& hi, unsigned long long v) {
    unsigned a, b;
    asm("mov.b64 {%0, %1}, %2;" : "=r"(a), "=r"(b) : "l"(v));
    lo = __uint_as_float(a); hi = __uint_as_float(b);
}
__device__ __forceinline__ unsigned long long add2(unsigned long long a, unsigned long long b) {
    unsigned long long r;
    asm("add.rn.f32x2 %0, %1, %2;" : "=l"(r) : "l"(a), "l"(b));
    return r;
}
__device__ __forceinline__ unsigned long long mul2(unsigned long long a, unsigned long long b) {
    unsigned long long r;
    asm("mul.rn.f32x2 %0, %1, %2;" : "=l"(r) : "l"(a), "l"(b));
    return r;
}

// ---------------- FPS: one block per batch, 512 threads x 8 points ----------------
// Exact XLA fp32 arithmetic: add.rn(x,-c) === sub.rn(x,c); mul/add chains per
// lane identical to scalar. First-occurrence argmax via redux.max(value bits,
// valid since all dists >= 0) + redux.min(global index among value-equal).
// Single barrier per iteration: parity-double-buffered warp partials.
__global__ void fps_kernel(const float* __restrict__ xyz, float* __restrict__ out) {
    extern __shared__ float sm[];
    float* sx = sm;
    float* sy = sm + NN;
    float* sz = sm + 2 * NN;
    __shared__ unsigned redv[2][16];
    __shared__ unsigned redi[2][16];

    int b = blockIdx.x;
    int t = threadIdx.x;
    int lane = t & 31, w = t >> 5;
    const float* base = xyz + (size_t)b * NN * 3;

    // 8 points/thread, pair i holds global indices (t + 1024*i, t + 1024*i + 512)
    unsigned long long px2[4], py2[4], pz2[4];
    float pd[8];
#pragma unroll
    for (int i = 0; i < 4; i++) {
        int n0 = t + 1024 * i;
        int n1 = n0 + 512;
        float x0 = base[n0 * 3 + 0], y0 = base[n0 * 3 + 1], z0 = base[n0 * 3 + 2];
        float x1 = base[n1 * 3 + 0], y1 = base[n1 * 3 + 1], z1 = base[n1 * 3 + 2];
        sx[n0] = x0; sy[n0] = y0; sz[n0] = z0;
        sx[n1] = x1; sy[n1] = y1; sz[n1] = z1;
        px2[i] = pack2(x0, x1);
        py2[i] = pack2(y0, y1);
        pz2[i] = pack2(z0, z1);
        pd[2 * i] = 1e10f; pd[2 * i + 1] = 1e10f;
    }
    __syncthreads();

    int far = 0;
    for (int s = 0; s < SS; s++) {
        float cx = sx[far], cy = sy[far], cz = sz[far];
        if (t == 0) {
            float* o = out + ((size_t)b * SS + s) * 3;
            o[0] = cx; o[1] = cy; o[2] = cz;
        }
        if (s == SS - 1) break;

        unsigned long long ncx = pack2(-cx, -cx);
        unsigned long long ncy = pack2(-cy, -cy);
        unsigned long long ncz = pack2(-cz, -cz);

        float bv = -1.0f; int bi = 0;
#pragma unroll
        for (int i = 0; i < 4; i++) {
            unsigned long long dx = add2(px2[i], ncx);   // == sub.rn
            unsigned long long dy = add2(py2[i], ncy);
            unsigned long long dz = add2(pz2[i], ncz);
            unsigned long long ss2 = add2(add2(mul2(dx, dx), mul2(dy, dy)), mul2(dz, dz));
            float d0, d1;
            unpack2(d0, d1, ss2);
            float n0v = fminf(pd[2 * i], d0);
            pd[2 * i] = n0v;
            if (n0v > bv) { bv = n0v; bi = t + 1024 * i; }       // ascending n order
            float n1v = fminf(pd[2 * i + 1], d1);
            pd[2 * i + 1] = n1v;
            if (n1v > bv) { bv = n1v; bi = t + 1024 * i + 512; }
        }
        // stage 1: warp max value, min global index among ties
        unsigned vb = __float_as_uint(bv);                 // bv >= 0: order-preserving
        unsigned mx = __reduce_max_sync(0xffffffffu, vb);
        unsigned cand = (vb == mx) ? (unsigned)bi : 0xffffffffu;
        unsigned mi = __reduce_min_sync(0xffffffffu, cand);

        int p = s & 1;
        if (lane == 0) { redv[p][w] = mx; redi[p][w] = mi; }
        __syncthreads();

        // stage 2: all warps redundantly over the 16 warp partials
        unsigned v2 = (lane < 16) ? redv[p][lane] : 0u;
        unsigned i2 = (lane < 16) ? redi[p][lane] : 0xffffffffu;
        unsigned m2 = __reduce_max_sync(0xffffffffu, v2);
        unsigned c2 = (v2 == m2) ? i2 : 0xffffffffu;
        far = (int)__reduce_min_sync(0xffffffffu, c2);
    }
}

// ---------------- kNN: 16 smallest of 4096, set semantics ----------------
__global__ void knn_kernel(const float* __restrict__ xyz,
                           const float* __restrict__ newxyz) {
    extern __shared__ unsigned char smraw[];
    float4* tile = (float4*)smraw;                 // 4096 float4
    float*  sdist = (float*)(tile + NN);           // [16][128]
    int*    sidx  = (int*)(sdist + 16 * 128);      // [16][128]

    int b = blockIdx.y;
    int t = threadIdx.x;
    const float* base = xyz + (size_t)b * NN * 3;
#pragma unroll 4
    for (int i = 0; i < NN / 128; i++) {
        int n = t + i * 128;
        float x = base[n * 3 + 0], y = base[n * 3 + 1], z = base[n * 3 + 2];
        tile[n] = make_float4(x, y, z, 0.5f * (x * x + y * y + z * z));
    }
    int sq = blockIdx.x * 128 + t;
    const float* q = newxyz + ((size_t)b * SS + sq) * 3;
    float qx = q[0], qy = q[1], qz = q[2];
    float qh = 0.5f * (qx * qx + qy * qy + qz * qz);
    float nqx = -qx, nqy = -qy, nqz = -qz;

#pragma unroll
    for (int sl = 0; sl < KNB; sl++) {
        sdist[sl * 128 + t] = 1e30f;
        sidx [sl * 128 + t] = 0;
    }
    __syncthreads();

    float maxv = 1e30f;
    int maxslot = 0;
    for (int j = 0; j < NN; j++) {
        float4 p = tile[j];
        float m = fmaf(nqx, p.x, fmaf(nqy, p.y, fmaf(nqz, p.z, qh + p.w)));
        if (m < maxv) {
            sdist[maxslot * 128 + t] = m;
            sidx [maxslot * 128 + t] = j;
            float mv = -1e30f; int ms = 0;
#pragma unroll
            for (int sl = 0; sl < KNB; sl++) {
                float d = sdist[sl * 128 + t];
                if (d > mv) { mv = d; ms = sl; }
            }
            maxv = mv; maxslot = ms;
        }
    }
    size_t rbase = ((size_t)b * SS + sq) * KNB;
#pragma unroll
    for (int sl = 0; sl < KNB; sl++)
        g_knn[rbase + sl] = sidx[sl * 128 + t];
}

// ---------------- gather: build X[M,72] = [pts 64 | dxyz 3 | pad 5], float4 ----------------
__global__ void gather_kernel(const float* __restrict__ xyz,
                              const float* __restrict__ pts,
                              const float* __restrict__ newxyz) {
    size_t gid = (size_t)blockIdx.x * 256 + threadIdx.x;   // row*18 + c4
    if (gid >= (size_t)MROWS * 18) return;
    int c4 = (int)(gid % 18);
    size_t row = gid / 18;
    size_t bs = row >> 4;          // b*S + s
    int b = (int)(bs >> 10);
    int n = g_knn[row];
    float4 v;
    if (c4 < 16) {
        v = ((const float4*)(pts + ((size_t)b * NN + n) * 64))[c4];
    } else if (c4 == 16) {
        const float* p = xyz + ((size_t)b * NN + n) * 3;
        const float* q = newxyz + bs * 3;
        v = make_float4(p[0] - q[0], p[1] - q[1], p[2] - q[2], 0.f);
    } else {
        v = make_float4(0.f, 0.f, 0.f, 0.f);
    }
    ((float4*)(g_X + row * XLD))[c4] = v;
}

// ---------------- GEMM: 128 rows x full N, weights smem-resident ----------------
template<bool USEBN>
__global__ __launch_bounds__(256) void gemm_kernel(
    const float* __restrict__ A, int lda,
    const float* __restrict__ W, int kreal, int nc, int perm,
    const float* __restrict__ bias,
    const float* __restrict__ gamma, const float* __restrict__ beta,
    int inlayer, int ncin,
    float* __restrict__ C, int ldc, int ktiles, int outlayer)
{
    extern __shared__ float sm[];
    float* sB    = sm;                 // [K8<=136][136]; reused as stats scratch
    float* sA    = sB + 136 * 136;     // [8][128]
    float* sBias = sA + 8 * 128;       // [144]
    float* sSc   = sBias + 144;        // [136]
    float* sSh   = sSc + 136;          // [136]

    int t = threadIdx.x;
    int K8 = ktiles * 8;

    for (int i = t; i < K8 * 136; i += 256) {
        int k = i / 136, c = i - k * 136;
        float wv = 0.f;
        if (k < kreal && c < nc) {
            int kk = perm ? (k < 64 ? k + 3 : k - 64) : k;
            wv = W[kk * nc + c];
        }
        sB[i] = wv;
    }
    if (t < 144) sBias[t] = (t < nc) ? bias[t] : 0.f;
    if (USEBN && t < 136) {
        float scv = 0.f, shv = 0.f;
        if (t < ncin) {
            const float inv = 1.0f / (float)MROWS;
            float m = g_sum[inlayer][t] * inv;
            float v = g_sq [inlayer][t] * inv - m * m;
            scv = gamma[t] * rsqrtf(v + 1e-5f);
            shv = beta[t] - m * scv;
        }
        sSc[t] = scv; sSh[t] = shv;
    }
    __syncthreads();

    int ty = t >> 4, tx = t & 15;
    size_t rowbase = (size_t)blockIdx.x * 128;
    int ar = t >> 1, aq = t & 1;

    float acc[8][9];
#pragma unroll
    for (int r = 0; r < 8; r++)
#pragma unroll
        for (int c = 0; c < 9; c++) acc[r][c] = 0.f;

    for (int kt = 0; kt < ktiles; kt++) {
        float4 v = *(const float4*)(A + (rowbase + ar) * lda + kt * 8 + aq * 4);
        if (USEBN) {
            int kb = kt * 8 + aq * 4;
            v.x = fmaxf(fmaf(v.x, sSc[kb + 0], sSh[kb + 0]), 0.f);
            v.y = fmaxf(fmaf(v.y, sSc[kb + 1], sSh[kb + 1]), 0.f);
            v.z = fmaxf(fmaf(v.z, sSc[kb + 2], sSh[kb + 2]), 0.f);
            v.w = fmaxf(fmaf(v.w, sSc[kb + 3], sSh[kb + 3]), 0.f);
        }
        __syncthreads();   // prev tile's sA fully consumed
        sA[(aq * 4 + 0) * 128 + ar] = v.x;
        sA[(aq * 4 + 1) * 128 + ar] = v.y;
        sA[(aq * 4 + 2) * 128 + ar] = v.z;
        sA[(aq * 4 + 3) * 128 + ar] = v.w;
        __syncthreads();

#pragma unroll
        for (int kk = 0; kk < 8; kk++) {
            float a[8], bf[9];
            const float* sak = sA + kk * 128 + ty * 8;
            *(float4*)(a)     = *(const float4*)(sak);
            *(float4*)(a + 4) = *(const float4*)(sak + 4);
            const float* sbk = sB + (kt * 8 + kk) * 136 + tx;
#pragma unroll
            for (int c = 0; c < 9; c++) bf[c] = sbk[c * 16];
#pragma unroll
            for (int r = 0; r < 8; r++)
#pragma unroll
                for (int c = 0; c < 9; c++)
                    acc[r][c] = fmaf(a[r], bf[c], acc[r][c]);
        }
    }

    // epilogue: store + per-thread column partial stats
    float s_[9], q_[9];
#pragma unroll
    for (int c = 0; c < 9; c++) { s_[c] = 0.f; q_[c] = 0.f; }
#pragma unroll
    for (int r = 0; r < 8; r++) {
        size_t row = rowbase + ty * 8 + r;
#pragma unroll
        for (int c = 0; c < 9; c++) {
            int col = tx + 16 * c;
            float val = acc[r][c] + sBias[col];
            s_[c] += val;
            q_[c] = fmaf(val, val, q_[c]);
            if (col < nc) C[row * ldc + col] = val;
        }
    }
    __syncthreads();                       // all warps done reading sB
#pragma unroll
    for (int c = 0; c < 9; c++) {
        int col = tx + 16 * c;
        sB[ty * 144 + col]        = s_[c];
        sB[2304 + ty * 144 + col] = q_[c];
    }
    __syncthreads();
    if (t < 144) {
        float s = 0.f, q = 0.f;
#pragma unroll
        for (int y = 0; y < 16; y++) {
            s += sB[y * 144 + t];
            q += sB[2304 + y * 144 + t];
        }
        atomicAdd(&g_sum[outlayer][t], s);
        atomicAdd(&g_sq [outlayer][t], q);
    }
}

// ---------------- final: relu(bn3(H3)+bnsc(SC)), max over K ----------------
__global__ void final_kernel(const float* __restrict__ g3, const float* __restrict__ b3,
                             const float* __restrict__ gsc, const float* __restrict__ bsc,
                             float* __restrict__ out) {
    int c = threadIdx.x;                 // 0..127
    size_t bs = blockIdx.x;              // 0..8191
    const float inv = 1.0f / (float)MROWS;
    float m = g_sum[2][c] * inv;
    float v = g_sq[2][c] * inv - m * m;
    float s3 = g3[c] * rsqrtf(v + 1e-5f);
    float h3 = b3[c] - m * s3;
    m = g_sum[3][c] * inv;
    v = g_sq[3][c] * inv - m * m;
    float ssc = gsc[c] * rsqrtf(v + 1e-5f);
    float hsc = bsc[c] - m * ssc;

    float mx = 0.0f;                     // relu output >= 0
    size_t base = bs * KNB;
#pragma unroll
    for (int kk = 0; kk < KNB; kk++) {
        float a  = fmaf(g_H3[(base + kk) * CO + c], s3, h3);
        float b2 = fmaf(g_SC[(base + kk) * CO + c], ssc, hsc);
        mx = fmaxf(mx, fmaxf(a + b2, 0.f));
    }
    out[24576 + bs * CO + c] = mx;
}

// ---------------- launch ----------------
extern "C" void kernel_launch(void* const* d_in, const int* in_sizes, int n_in,
                              void* d_out, int out_size) {
    const float* xyz   = (const float*)d_in[0];
    const float* pts   = (const float*)d_in[1];
    const float* fc1_w = (const float*)d_in[2];
    const float* fc1_b = (const float*)d_in[3];
    const float* bn1_g = (const float*)d_in[4];
    const float* bn1_b = (const float*)d_in[5];
    const float* fc2_w = (const float*)d_in[6];
    const float* fc2_b = (const float*)d_in[7];
    const float* bn2_g = (const float*)d_in[8];
    const float* bn2_b = (const float*)d_in[9];
    const float* fc3_w = (const float*)d_in[10];
    const float* fc3_b = (const float*)d_in[11];
    const float* bn3_g = (const float*)d_in[12];
    const float* bn3_b = (const float*)d_in[13];
    const float* sc_w  = (const float*)d_in[14];
    const float* sc_b  = (const float*)d_in[15];
    const float* scbn_g = (const float*)d_in[16];
    const float* scbn_b = (const float*)d_in[17];
    float* out = (float*)d_out;

    void *pX, *pH1, *pH2, *pH3, *pSC;
    cudaGetSymbolAddress(&pX,  g_X);
    cudaGetSymbolAddress(&pH1, g_H1);
    cudaGetSymbolAddress(&pH2, g_H2);
    cudaGetSymbolAddress(&pH3, g_H3);
    cudaGetSymbolAddress(&pSC, g_SC);
    float* X  = (float*)pX;
    float* H1 = (float*)pH1;
    float* H2 = (float*)pH2;
    float* H3 = (float*)pH3;
    float* SC = (float*)pSC;

    const int fps_smem  = 3 * NN * 4;                              // 49152
    const int knn_smem  = NN * 16 + 16 * 128 * 4 * 2;              // 81920
    const int gemm_smem = (136 * 136 + 8 * 128 + 144 + 136 * 2) * 4; // 79744

    cudaFuncSetAttribute(fps_kernel,  cudaFuncAttributeMaxDynamicSharedMemorySize, fps_smem);
    cudaFuncSetAttribute(knn_kernel,  cudaFuncAttributeMaxDynamicSharedMemorySize, knn_smem);
    cudaFuncSetAttribute(gemm_kernel<false>, cudaFuncAttributeMaxDynamicSharedMemorySize, gemm_smem);
    cudaFuncSetAttribute(gemm_kernel<true>,  cudaFuncAttributeMaxDynamicSharedMemorySize, gemm_smem);

    zero_stats_kernel<<<1, 1024>>>();
    fps_kernel<<<BB, 512, fps_smem>>>(xyz, out);
    knn_kernel<<<dim3(SS / 128, BB), 128, knn_smem>>>(xyz, out);
    gather_kernel<<<(MROWS * 18) / 256, 256>>>(xyz, pts, out);

    // layer 1: H1 = X @ fc1_w + b            (K=67 perm, N=134) -> stats[0]
    gemm_kernel<false><<<MROWS / 128, 256, gemm_smem>>>(
        X, XLD, fc1_w, 67, 134, 1, fc1_b, nullptr, nullptr, 0, 0, H1, HLD, 9, 0);

    // shortcut: SC = X @ sc_w + b            (K=67 perm, N=128) -> stats[3]
    gemm_kernel<false><<<MROWS / 128, 256, gemm_smem>>>(
        X, XLD, sc_w, 67, 128, 1, sc_b, nullptr, nullptr, 0, 0, SC, CO, 9, 3);

    // layer 2: H2 = relu(bn1(H1)) @ fc2_w + b  (K=134, N=134) -> stats[1]
    gemm_kernel<true><<<MROWS / 128, 256, gemm_smem>>>(
        H1, HLD, fc2_w, 134, 134, 0, fc2_b, bn1_g, bn1_b, 0, 134, H2, HLD, 17, 1);

    // layer 3: H3 = relu(bn2(H2)) @ fc3_w + b  (K=134, N=128) -> stats[2]
    gemm_kernel<true><<<MROWS / 128, 256, gemm_smem>>>(
        H2, HLD, fc3_w, 134, 128, 0, fc3_b, bn2_g, bn2_b, 1, 134, H3, CO, 17, 2);

    final_kernel<<<BB * SS, 128>>>(bn3_g, bn3_b, scbn_g, scbn_b, out);
}

// round 14
// speedup vs baseline: 1.5357x; 1.1538x over previous
#include <cuda_runtime.h>
#include <cuda_bf16.h>
#include <cstdint>

#define BB 8
#define NN 4096
#define SS 1024
#define KNB 16
#define MROWS (BB*SS*KNB)      /* 131072 */
#define XLD 72                 /* [pts 64 | dxyz 3 | pad 5] */
#define HLD 136
#define CO  128

// ---------------- device scratch ----------------
__device__ float g_X [(size_t)MROWS * XLD];
__device__ float g_H1[(size_t)MROWS * HLD];
__device__ float g_H2[(size_t)MROWS * HLD];
__device__ float g_H3[(size_t)MROWS * CO];
__device__ float g_SC[(size_t)MROWS * CO];
__device__ int   g_knn[(size_t)MROWS];
__device__ float g_sum[4][160];
__device__ float g_sq [4][160];
// weight images: B[n][k] bf16 hi/lo, row pitch P (88 or 152)
// L1@0 (136x88), SC@11968 (136x88), L2@23936 (136x152), L3@44608 (136x152)
__device__ __nv_bfloat16 g_BimgHi[65280];
__device__ __nv_bfloat16 g_BimgLo[65280];

// ---------------- helpers ----------------
__device__ __forceinline__ uint32_t smem_u32(const void* p) {
    uint32_t a;
    asm("{ .reg .u64 t; cvta.to.shared.u64 t, %1; cvt.u32.u64 %0, t; }" : "=r"(a) : "l"(p));
    return a;
}
__device__ __forceinline__ uint32_t lds32(uint32_t addr) {
    uint32_t v;
    asm volatile("ld.shared.b32 %0, [%1];" : "=r"(v) : "r"(addr));
    return v;
}
__device__ __forceinline__ void mma_bf16(float* c, const uint32_t* a, uint32_t b0, uint32_t b1) {
    asm volatile("mma.sync.aligned.m16n8k16.row.col.f32.bf16.bf16.f32 "
        "{%0,%1,%2,%3}, {%4,%5,%6,%7}, {%8,%9}, {%0,%1,%2,%3};"
        : "+f"(c[0]), "+f"(c[1]), "+f"(c[2]), "+f"(c[3])
        : "r"(a[0]), "r"(a[1]), "r"(a[2]), "r"(a[3]), "r"(b0), "r"(b1));
}

// ---------------- packed f32x2 helpers (FPS) ----------------
__device__ __forceinline__ unsigned long long pack2(float lo, float hi) {
    unsigned long long r;
    asm("mov.b64 %0, {%1, %2};" : "=l"(r) : "r"(__float_as_uint(lo)), "r"(__float_as_uint(hi)));
    return r;
}
__device__ __forceinline__ void unpack2(float& lo, float& hi, unsigned long long v) {
    unsigned a, b;
    asm("mov.b64 {%0, %1}, %2;" : "=r"(a), "=r"(b) : "l"(v));
    lo = __uint_as_float(a); hi = __uint_as_float(b);
}
__device__ __forceinline__ unsigned long long add2(unsigned long long a, unsigned long long b) {
    unsigned long long r;
    asm("add.rn.f32x2 %0, %1, %2;" : "=l"(r) : "l"(a), "l"(b));
    return r;
}
__device__ __forceinline__ unsigned long long mul2(unsigned long long a, unsigned long long b) {
    unsigned long long r;
    asm("mul.rn.f32x2 %0, %1, %2;" : "=l"(r) : "l"(a), "l"(b));
    return r;
}

// ---------------- prep: zero stats + build weight images ----------------
__global__ void prep_kernel(const float* __restrict__ fc1_w, const float* __restrict__ sc_w,
                            const float* __restrict__ fc2_w, const float* __restrict__ fc3_w) {
    int idx = blockIdx.x * 256 + threadIdx.x;
    if (idx < 640) {
        (&g_sum[0][0])[idx] = 0.f;
        (&g_sq [0][0])[idx] = 0.f;
    }
    if (idx >= 65280) return;
    const float* W; int e, P, nc, perm, off;
    if (idx < 11968)      { e = idx;         W = fc1_w; P = 88;  nc = 134; perm = 1; off = 0; }
    else if (idx < 23936) { e = idx - 11968; W = sc_w;  P = 88;  nc = 128; perm = 1; off = 11968; }
    else if (idx < 44608) { e = idx - 23936; W = fc2_w; P = 152; nc = 134; perm = 0; off = 23936; }
    else                  { e = idx - 44608; W = fc3_w; P = 152; nc = 128; perm = 0; off = 44608; }
    int n = e / P, k = e % P;
    int src = perm ? (k < 64 ? k + 3 : (k < 67 ? k - 64 : -1)) : (k < 134 ? k : -1);
    float v = (src >= 0 && n < nc) ? W[src * nc + n] : 0.f;
    __nv_bfloat16 h = __float2bfloat16(v);
    __nv_bfloat16 l = __float2bfloat16(v - __bfloat162float(h));
    g_BimgHi[off + e] = h;
    g_BimgLo[off + e] = l;
}

// ---------------- FPS (unchanged) ----------------
__global__ void fps_kernel(const float* __restrict__ xyz, float* __restrict__ out) {
    extern __shared__ float sm[];
    float* sx = sm;
    float* sy = sm + NN;
    float* sz = sm + 2 * NN;
    __shared__ unsigned redv[2][16];
    __shared__ unsigned redi[2][16];

    int b = blockIdx.x;
    int t = threadIdx.x;
    int lane = t & 31, w = t >> 5;
    const float* base = xyz + (size_t)b * NN * 3;

    unsigned long long px2[4], py2[4], pz2[4];
    float pd[8];
#pragma unroll
    for (int i = 0; i < 4; i++) {
        int n0 = t + 1024 * i, n1 = n0 + 512;
        float x0 = base[n0*3], y0 = base[n0*3+1], z0 = base[n0*3+2];
        float x1 = base[n1*3], y1 = base[n1*3+1], z1 = base[n1*3+2];
        sx[n0]=x0; sy[n0]=y0; sz[n0]=z0;
        sx[n1]=x1; sy[n1]=y1; sz[n1]=z1;
        px2[i]=pack2(x0,x1); py2[i]=pack2(y0,y1); pz2[i]=pack2(z0,z1);
        pd[2*i]=1e10f; pd[2*i+1]=1e10f;
    }
    __syncthreads();

    int far = 0;
    for (int s = 0; s < SS; s++) {
        float cx = sx[far], cy = sy[far], cz = sz[far];
        if (t == 0) {
            float* o = out + ((size_t)b * SS + s) * 3;
            o[0]=cx; o[1]=cy; o[2]=cz;
        }
        if (s == SS - 1) break;

        unsigned long long ncx = pack2(-cx,-cx), ncy = pack2(-cy,-cy), ncz = pack2(-cz,-cz);
        float bv = -1.0f; int bi = 0;
#pragma unroll
        for (int i = 0; i < 4; i++) {
            unsigned long long dx = add2(px2[i], ncx);
            unsigned long long dy = add2(py2[i], ncy);
            unsigned long long dz = add2(pz2[i], ncz);
            unsigned long long ss2 = add2(add2(mul2(dx,dx), mul2(dy,dy)), mul2(dz,dz));
            float d0, d1; unpack2(d0, d1, ss2);
            float n0v = fminf(pd[2*i], d0); pd[2*i] = n0v;
            if (n0v > bv) { bv = n0v; bi = t + 1024*i; }
            float n1v = fminf(pd[2*i+1], d1); pd[2*i+1] = n1v;
            if (n1v > bv) { bv = n1v; bi = t + 1024*i + 512; }
        }
        unsigned vb = __float_as_uint(bv);
        unsigned mx = __reduce_max_sync(0xffffffffu, vb);
        unsigned cand = (vb == mx) ? (unsigned)bi : 0xffffffffu;
        unsigned mi = __reduce_min_sync(0xffffffffu, cand);

        int p = s & 1;
        if (lane == 0) { redv[p][w] = mx; redi[p][w] = mi; }
        __syncthreads();
        unsigned v2 = (lane < 16) ? redv[p][lane] : 0u;
        unsigned i2 = (lane < 16) ? redi[p][lane] : 0xffffffffu;
        unsigned m2 = __reduce_max_sync(0xffffffffu, v2);
        unsigned c2 = (v2 == m2) ? i2 : 0xffffffffu;
        far = (int)__reduce_min_sync(0xffffffffu, c2);
    }
}

// ---------------- kNN (unchanged) ----------------
__global__ void knn_kernel(const float* __restrict__ xyz,
                           const float* __restrict__ newxyz) {
    extern __shared__ unsigned char smraw[];
    float4* tile = (float4*)smraw;
    float*  sdist = (float*)(tile + NN);
    int*    sidx  = (int*)(sdist + 16 * 128);

    int b = blockIdx.y;
    int t = threadIdx.x;
    const float* base = xyz + (size_t)b * NN * 3;
#pragma unroll 4
    for (int i = 0; i < NN / 128; i++) {
        int n = t + i * 128;
        float x = base[n*3], y = base[n*3+1], z = base[n*3+2];
        tile[n] = make_float4(x, y, z, 0.5f*(x*x + y*y + z*z));
    }
    int sq = blockIdx.x * 128 + t;
    const float* q = newxyz + ((size_t)b * SS + sq) * 3;
    float qx=q[0], qy=q[1], qz=q[2];
    float qh = 0.5f*(qx*qx + qy*qy + qz*qz);
    float nqx=-qx, nqy=-qy, nqz=-qz;

#pragma unroll
    for (int sl = 0; sl < KNB; sl++) { sdist[sl*128+t] = 1e30f; sidx[sl*128+t] = 0; }
    __syncthreads();

    float maxv = 1e30f; int maxslot = 0;
    for (int j = 0; j < NN; j++) {
        float4 p = tile[j];
        float m = fmaf(nqx, p.x, fmaf(nqy, p.y, fmaf(nqz, p.z, qh + p.w)));
        if (m < maxv) {
            sdist[maxslot*128+t] = m;
            sidx [maxslot*128+t] = j;
            float mv = -1e30f; int ms = 0;
#pragma unroll
            for (int sl = 0; sl < KNB; sl++) {
                float d = sdist[sl*128+t];
                if (d > mv) { mv = d; ms = sl; }
            }
            maxv = mv; maxslot = ms;
        }
    }
    size_t rbase = ((size_t)b * SS + sq) * KNB;
#pragma unroll
    for (int sl = 0; sl < KNB; sl++)
        g_knn[rbase + sl] = sidx[sl*128+t];
}

// ---------------- gather (unchanged) ----------------
__global__ void gather_kernel(const float* __restrict__ xyz,
                              const float* __restrict__ pts,
                              const float* __restrict__ newxyz) {
    size_t gid = (size_t)blockIdx.x * 256 + threadIdx.x;
    if (gid >= (size_t)MROWS * 18) return;
    int c4 = (int)(gid % 18);
    size_t row = gid / 18;
    size_t bs = row >> 4;
    int b = (int)(bs >> 10);
    int n = g_knn[row];
    float4 v;
    if (c4 < 16) {
        v = ((const float4*)(pts + ((size_t)b * NN + n) * 64))[c4];
    } else if (c4 == 16) {
        const float* p = xyz + ((size_t)b * NN + n) * 3;
        const float* q = newxyz + bs * 3;
        v = make_float4(p[0]-q[0], p[1]-q[1], p[2]-q[2], 0.f);
    } else {
        v = make_float4(0.f, 0.f, 0.f, 0.f);
    }
    ((float4*)(g_X + row * XLD))[c4] = v;
}

// ---------------- HMMA GEMM: C[128 x <=136] = act(A) @ W + bias ----------------
// smem: sBias[144]@0 | sSc[136]@576 | sSh[136]@1120 | sSum[136]@1664 | sSq[136]@2208
//       AH@2752 [128][P] bf16 | AL | BH [136][P] bf16 | BL
// fragments loaded with direct ld.shared (pitch 2P bytes == 48 mod 128 -> conflict-free)
template<bool USEBN>
__global__ __launch_bounds__(256) void tgemm_kernel(
    const float* __restrict__ A, int lda, int P, int ksteps,
    const __nv_bfloat16* __restrict__ BHg, const __nv_bfloat16* __restrict__ BLg,
    const float* __restrict__ bias, int nc,
    const float* __restrict__ gamma, const float* __restrict__ beta, int inlayer,
    float* __restrict__ C, int ldc, int outlayer)
{
    extern __shared__ char smc[];
    float* sBias = (float*)smc;
    float* sSc   = (float*)(smc + 576);
    float* sSh   = (float*)(smc + 1120);
    float* sSum  = (float*)(smc + 1664);
    float* sSq   = (float*)(smc + 2208);
    char* AH = smc + 2752;
    const int asz = 128 * P * 2;
    const int bsz = 136 * P * 2;
    char* AL = AH + asz;
    char* BHs = AL + asz;
    char* BLs = BHs + bsz;

    int t = threadIdx.x;

    if (t < 144) sBias[t] = (t < nc) ? bias[t] : 0.f;
    if (t < 136) {
        sSum[t] = 0.f; sSq[t] = 0.f;
        if (USEBN) {
            float scv = 0.f, shv = 0.f;
            if (t < 134) {
                const float inv = 1.0f / (float)MROWS;
                float m = g_sum[inlayer][t] * inv;
                float v = g_sq [inlayer][t] * inv - m * m;
                scv = gamma[t] * rsqrtf(v + 1e-5f);
                shv = beta[t] - m * scv;
            }
            sSc[t] = scv; sSh[t] = shv;
        }
    }
    // copy B images (flat, 16B)
    {
        int n16 = bsz >> 4;
        const float4* bh4 = (const float4*)BHg;
        const float4* bl4 = (const float4*)BLg;
        for (int i = t; i < n16; i += 256) {
            ((float4*)BHs)[i] = bh4[i];
            ((float4*)BLs)[i] = bl4[i];
        }
    }
    __syncthreads();   // sSc/sSh ready before A staging

    // stage A: row = t/2, k-half = t&1; bn+relu fused; bf16 hi/lo split
    {
        int row = t >> 1;
        int halfbase = (t & 1) * (P >> 1);
        const float* arow = A + ((size_t)blockIdx.x * 128 + row) * lda;
        int nf4 = P >> 3;
        for (int i = 0; i < nf4; i++) {
            int k = halfbase + i * 4;
            float4 v = make_float4(0.f, 0.f, 0.f, 0.f);
            if (k < lda) {
                v = *(const float4*)(arow + k);
                if (USEBN) {
                    v.x = fmaxf(fmaf(v.x, sSc[k+0], sSh[k+0]), 0.f);
                    v.y = fmaxf(fmaf(v.y, sSc[k+1], sSh[k+1]), 0.f);
                    v.z = fmaxf(fmaf(v.z, sSc[k+2], sSh[k+2]), 0.f);
                    v.w = fmaxf(fmaf(v.w, sSc[k+3], sSh[k+3]), 0.f);
                }
            }
            __nv_bfloat162 h01 = __floats2bfloat162_rn(v.x, v.y);
            __nv_bfloat162 h23 = __floats2bfloat162_rn(v.z, v.w);
            __nv_bfloat162 l01 = __floats2bfloat162_rn(v.x - __bfloat162float(h01.x),
                                                       v.y - __bfloat162float(h01.y));
            __nv_bfloat162 l23 = __floats2bfloat162_rn(v.z - __bfloat162float(h23.x),
                                                       v.w - __bfloat162float(h23.y));
            size_t o = ((size_t)row * P + k) * 2;
            *(__nv_bfloat162*)(AH + o)     = h01;
            *(__nv_bfloat162*)(AH + o + 4) = h23;
            *(__nv_bfloat162*)(AL + o)     = l01;
            *(__nv_bfloat162*)(AL + o + 4) = l23;
        }
    }
    __syncthreads();

    // ---- MMA mainloop ----
    uint32_t sb = smem_u32(smc);
    uint32_t aHb = sb + 2752;
    uint32_t aLb = aHb + asz;
    uint32_t bHb = aLb + asz;
    uint32_t bLb = bHb + bsz;

    int wid = t >> 5, lane = t & 31;
    int g = lane >> 2, tg = lane & 3;
    int mg = wid & 3, ng = wid >> 2;
    int nbase = ng * 72;
    int ntiles = ng ? 8 : 9;
    uint32_t P2 = (uint32_t)P * 2;

    float acc[2][9][4];
#pragma unroll
    for (int mt = 0; mt < 2; mt++)
#pragma unroll
        for (int nt = 0; nt < 9; nt++)
#pragma unroll
            for (int i = 0; i < 4; i++) acc[mt][nt][i] = 0.f;

    for (int ks = 0; ks < ksteps; ks++) {
        uint32_t kboff = (uint32_t)(ks * 16 + tg * 2) * 2;
        uint32_t ah[2][4], al[2][4];
#pragma unroll
        for (int mt = 0; mt < 2; mt++) {
            uint32_t r0 = (uint32_t)(mg * 32 + mt * 16 + g);
            uint32_t b0 = r0 * P2 + kboff;
            uint32_t b1 = b0 + 8 * P2;
            ah[mt][0] = lds32(aHb + b0);      ah[mt][1] = lds32(aHb + b1);
            ah[mt][2] = lds32(aHb + b0 + 16); ah[mt][3] = lds32(aHb + b1 + 16);
            al[mt][0] = lds32(aLb + b0);      al[mt][1] = lds32(aLb + b1);
            al[mt][2] = lds32(aLb + b0 + 16); al[mt][3] = lds32(aLb + b1 + 16);
        }
#pragma unroll
        for (int nt = 0; nt < 9; nt++) {
            if (nt >= ntiles) break;
            uint32_t n0 = (uint32_t)(nbase + nt * 8 + g);
            uint32_t bb = n0 * P2 + kboff;
            uint32_t bh0 = lds32(bHb + bb), bh1 = lds32(bHb + bb + 16);
            uint32_t bl0 = lds32(bLb + bb), bl1 = lds32(bLb + bb + 16);
#pragma unroll
            for (int mt = 0; mt < 2; mt++) {
                mma_bf16(acc[mt][nt], ah[mt], bh0, bh1);
                mma_bf16(acc[mt][nt], ah[mt], bl0, bl1);
                mma_bf16(acc[mt][nt], al[mt], bh0, bh1);
            }
        }
    }

    // ---- epilogue: bias + store + column stats ----
    size_t rg0 = (size_t)blockIdx.x * 128 + mg * 32 + g;
#pragma unroll
    for (int nt = 0; nt < 9; nt++) {
        if (nt >= ntiles) break;
        int cb = nbase + nt * 8;
        int c0 = cb + tg * 2;
        float b0v = sBias[c0], b1v = sBias[c0 + 1];
        float s0 = 0.f, s1 = 0.f, q0 = 0.f, q1 = 0.f;
#pragma unroll
        for (int mt = 0; mt < 2; mt++) {
            float* cc = acc[mt][nt];
            float v0 = cc[0] + b0v, v1 = cc[1] + b1v;
            float v2 = cc[2] + b0v, v3 = cc[3] + b1v;
            if (cb < ldc) {
                size_t r0 = rg0 + mt * 16;
                float2 w0 = make_float2(v0, v1);
                float2 w1 = make_float2(v2, v3);
                *(float2*)(C + r0 * ldc + c0) = w0;
                *(float2*)(C + (r0 + 8) * ldc + c0) = w1;
            }
            s0 += v0 + v2; s1 += v1 + v3;
            q0 += v0 * v0 + v2 * v2; q1 += v1 * v1 + v3 * v3;
        }
#pragma unroll
        for (int off = 16; off >= 4; off >>= 1) {
            s0 += __shfl_down_sync(0xffffffffu, s0, off);
            s1 += __shfl_down_sync(0xffffffffu, s1, off);
            q0 += __shfl_down_sync(0xffffffffu, q0, off);
            q1 += __shfl_down_sync(0xffffffffu, q1, off);
        }
        if (lane < 4) {
            atomicAdd(&sSum[c0], s0); atomicAdd(&sSum[c0 + 1], s1);
            atomicAdd(&sSq [c0], q0); atomicAdd(&sSq [c0 + 1], q1);
        }
    }
    __syncthreads();
    if (t < 136) {
        atomicAdd(&g_sum[outlayer][t], sSum[t]);
        atomicAdd(&g_sq [outlayer][t], sSq[t]);
    }
}

// ---------------- final: relu(bn3(H3)+bnsc(SC)), max over K ----------------
__global__ void final_kernel(const float* __restrict__ g3, const float* __restrict__ b3,
                             const float* __restrict__ gsc, const float* __restrict__ bsc,
                             float* __restrict__ out) {
    int c = threadIdx.x;
    size_t bs = blockIdx.x;
    const float inv = 1.0f / (float)MROWS;
    float m = g_sum[2][c] * inv;
    float v = g_sq[2][c] * inv - m * m;
    float s3 = g3[c] * rsqrtf(v + 1e-5f);
    float h3 = b3[c] - m * s3;
    m = g_sum[3][c] * inv;
    v = g_sq[3][c] * inv - m * m;
    float ssc = gsc[c] * rsqrtf(v + 1e-5f);
    float hsc = bsc[c] - m * ssc;

    float mx = 0.0f;
    size_t base = bs * KNB;
#pragma unroll
    for (int kk = 0; kk < KNB; kk++) {
        float a  = fmaf(g_H3[(base + kk) * CO + c], s3, h3);
        float b2 = fmaf(g_SC[(base + kk) * CO + c], ssc, hsc);
        mx = fmaxf(mx, fmaxf(a + b2, 0.f));
    }
    out[24576 + bs * CO + c] = mx;
}

// ---------------- launch ----------------
extern "C" void kernel_launch(void* const* d_in, const int* in_sizes, int n_in,
                              void* d_out, int out_size) {
    const float* xyz   = (const float*)d_in[0];
    const float* pts   = (const float*)d_in[1];
    const float* fc1_w = (const float*)d_in[2];
    const float* fc1_b = (const float*)d_in[3];
    const float* bn1_g = (const float*)d_in[4];
    const float* bn1_b = (const float*)d_in[5];
    const float* fc2_w = (const float*)d_in[6];
    const float* fc2_b = (const float*)d_in[7];
    const float* bn2_g = (const float*)d_in[8];
    const float* bn2_b = (const float*)d_in[9];
    const float* fc3_w = (const float*)d_in[10];
    const float* fc3_b = (const float*)d_in[11];
    const float* bn3_g = (const float*)d_in[12];
    const float* bn3_b = (const float*)d_in[13];
    const float* sc_w  = (const float*)d_in[14];
    const float* sc_b  = (const float*)d_in[15];
    const float* scbn_g = (const float*)d_in[16];
    const float* scbn_b = (const float*)d_in[17];
    float* out = (float*)d_out;

    void *pX, *pH1, *pH2, *pH3, *pSC, *pBH, *pBL;
    cudaGetSymbolAddress(&pX,  g_X);
    cudaGetSymbolAddress(&pH1, g_H1);
    cudaGetSymbolAddress(&pH2, g_H2);
    cudaGetSymbolAddress(&pH3, g_H3);
    cudaGetSymbolAddress(&pSC, g_SC);
    cudaGetSymbolAddress(&pBH, g_BimgHi);
    cudaGetSymbolAddress(&pBL, g_BimgLo);
    float* X  = (float*)pX;
    float* H1 = (float*)pH1;
    float* H2 = (float*)pH2;
    float* H3 = (float*)pH3;
    float* SC = (float*)pSC;
    __nv_bfloat16* BH = (__nv_bfloat16*)pBH;
    __nv_bfloat16* BL = (__nv_bfloat16*)pBL;

    const int fps_smem = 3 * NN * 4;
    const int knn_smem = NN * 16 + 16 * 128 * 4 * 2;
    const int sm88  = 2752 + 88  * 1056;   // 95680
    const int sm152 = 2752 + 152 * 1056;   // 163264

    cudaFuncSetAttribute(fps_kernel, cudaFuncAttributeMaxDynamicSharedMemorySize, fps_smem);
    cudaFuncSetAttribute(knn_kernel, cudaFuncAttributeMaxDynamicSharedMemorySize, knn_smem);
    cudaFuncSetAttribute(tgemm_kernel<false>, cudaFuncAttributeMaxDynamicSharedMemorySize, sm152);
    cudaFuncSetAttribute(tgemm_kernel<true>,  cudaFuncAttributeMaxDynamicSharedMemorySize, sm152);

    prep_kernel<<<255, 256>>>(fc1_w, sc_w, fc2_w, fc3_w);
    fps_kernel<<<BB, 512, fps_smem>>>(xyz, out);
    knn_kernel<<<dim3(SS / 128, BB), 128, knn_smem>>>(xyz, out);
    gather_kernel<<<(MROWS * 18) / 256, 256>>>(xyz, pts, out);

    // L1: H1 = X @ fc1_w + b   -> stats[0]
    tgemm_kernel<false><<<MROWS / 128, 256, sm88>>>(
        X, XLD, 88, 5, BH + 0, BL + 0, fc1_b, 134,
        nullptr, nullptr, 0, H1, HLD, 0);
    // SC: SC = X @ sc_w + b    -> stats[3]
    tgemm_kernel<false><<<MROWS / 128, 256, sm88>>>(
        X, XLD, 88, 5, BH + 11968, BL + 11968, sc_b, 128,
        nullptr, nullptr, 0, SC, CO, 3);
    // L2: H2 = relu(bn1(H1)) @ fc2_w + b  -> stats[1]
    tgemm_kernel<true><<<MROWS / 128, 256, sm152>>>(
        H1, HLD, 152, 9, BH + 23936, BL + 23936, fc2_b, 134,
        bn1_g, bn1_b, 0, H2, HLD, 1);
    // L3: H3 = relu(bn2(H2)) @ fc3_w + b  -> stats[2]
    tgemm_kernel<true><<<MROWS / 128, 256, sm152>>>(
        H2, HLD, 152, 9, BH + 44608, BL + 44608, fc3_b, 128,
        bn2_g, bn2_b, 1, H3, CO, 2);

    final_kernel<<<BB * SS, 128>>>(bn3_g, bn3_b, scbn_g, scbn_b, out);
}

// round 16
// speedup vs baseline: 1.6744x; 1.0903x over previous
#include <cuda_runtime.h>
#include <cuda_bf16.h>
#include <cstdint>

#define BB 8
#define NN 4096
#define SS 1024
#define KNB 16
#define MROWS (BB*SS*KNB)      /* 131072 */
#define XLD 72                 /* [pts 64 | dxyz 3 | pad 5] */
#define HLD 136
#define CO  128

// ---------------- device scratch ----------------
__device__ float g_X [(size_t)MROWS * XLD];
__device__ float g_H1[(size_t)MROWS * HLD];
__device__ float g_H2[(size_t)MROWS * HLD];
__device__ float g_H3[(size_t)MROWS * CO];
__device__ float g_SC[(size_t)MROWS * CO];
__device__ float g_sum[4][160];
__device__ float g_sq [4][160];
// weight images: B[n][k] bf16 hi/lo, row pitch P (88 or 152)
// L1@0 (136x88), SC@11968 (136x88), L2@23936 (136x152), L3@44608 (136x152)
__device__ __nv_bfloat16 g_BimgHi[65280];
__device__ __nv_bfloat16 g_BimgLo[65280];

// ---------------- helpers ----------------
__device__ __forceinline__ uint32_t smem_u32(const void* p) {
    uint32_t a;
    asm("{ .reg .u64 t; cvta.to.shared.u64 t, %1; cvt.u32.u64 %0, t; }" : "=r"(a) : "l"(p));
    return a;
}
__device__ __forceinline__ uint32_t lds32(uint32_t addr) {
    uint32_t v;
    asm volatile("ld.shared.b32 %0, [%1];" : "=r"(v) : "r"(addr));
    return v;
}
__device__ __forceinline__ void mma_bf16(float* c, const uint32_t* a, uint32_t b0, uint32_t b1) {
    asm volatile("mma.sync.aligned.m16n8k16.row.col.f32.bf16.bf16.f32 "
        "{%0,%1,%2,%3}, {%4,%5,%6,%7}, {%8,%9}, {%0,%1,%2,%3};"
        : "+f"(c[0]), "+f"(c[1]), "+f"(c[2]), "+f"(c[3])
        : "r"(a[0]), "r"(a[1]), "r"(a[2]), "r"(a[3]), "r"(b0), "r"(b1));
}

// ---------------- packed f32x2 helpers (FPS) ----------------
__device__ __forceinline__ unsigned long long pack2(float lo, float hi) {
    unsigned long long r;
    asm("mov.b64 %0, {%1, %2};" : "=l"(r) : "r"(__float_as_uint(lo)), "r"(__float_as_uint(hi)));
    return r;
}
__device__ __forceinline__ void unpack2(float& lo, float& hi, unsigned long long v) {
    unsigned a, b;
    asm("mov.b64 {%0, %1}, %2;" : "=r"(a), "=r"(b) : "l"(v));
    lo = __uint_as_float(a); hi = __uint_as_float(b);
}
__device__ __forceinline__ unsigned long long add2(unsigned long long a, unsigned long long b) {
    unsigned long long r;
    asm("add.rn.f32x2 %0, %1, %2;" : "=l"(r) : "l"(a), "l"(b));
    return r;
}
__device__ __forceinline__ unsigned long long mul2(unsigned long long a, unsigned long long b) {
    unsigned long long r;
    asm("mul.rn.f32x2 %0, %1, %2;" : "=l"(r) : "l"(a), "l"(b));
    return r;
}

// ---------------- prep: zero stats + build weight images ----------------
__global__ void prep_kernel(const float* __restrict__ fc1_w, const float* __restrict__ sc_w,
                            const float* __restrict__ fc2_w, const float* __restrict__ fc3_w) {
    int idx = blockIdx.x * 256 + threadIdx.x;
    if (idx < 640) {
        (&g_sum[0][0])[idx] = 0.f;
        (&g_sq [0][0])[idx] = 0.f;
    }
    if (idx >= 65280) return;
    const float* W; int e, P, nc, perm, off;
    if (idx < 11968)      { e = idx;         W = fc1_w; P = 88;  nc = 134; perm = 1; off = 0; }
    else if (idx < 23936) { e = idx - 11968; W = sc_w;  P = 88;  nc = 128; perm = 1; off = 11968; }
    else if (idx < 44608) { e = idx - 23936; W = fc2_w; P = 152; nc = 134; perm = 0; off = 23936; }
    else                  { e = idx - 44608; W = fc3_w; P = 152; nc = 128; perm = 0; off = 44608; }
    int n = e / P, k = e % P;
    int src = perm ? (k < 64 ? k + 3 : (k < 67 ? k - 64 : -1)) : (k < 134 ? k : -1);
    float v = (src >= 0 && n < nc) ? W[src * nc + n] : 0.f;
    __nv_bfloat16 h = __float2bfloat16(v);
    __nv_bfloat16 l = __float2bfloat16(v - __bfloat162float(h));
    g_BimgHi[off + e] = h;
    g_BimgLo[off + e] = l;
}

// ---------------- FPS: 512 threads x 8 pts, pre-negated, float4 smem ----------------
// Exact XLA fp32: add.rn(c,-p) == sub.rn(p,c) up to sign; squares identical.
__global__ void fps_kernel(const float* __restrict__ xyz, float* __restrict__ out) {
    extern __shared__ float4 sxyz[];              // [4096]
    __shared__ unsigned redv[2][16];
    __shared__ unsigned redi[2][16];

    int b = blockIdx.x;
    int t = threadIdx.x;
    int lane = t & 31, w = t >> 5;
    const float* base = xyz + (size_t)b * NN * 3;

    unsigned long long px2[4], py2[4], pz2[4];    // NEGATED coords, packed pairs
    float pd[8];
#pragma unroll
    for (int i = 0; i < 4; i++) {
        int n0 = t + 1024 * i, n1 = n0 + 512;
        float x0 = base[n0*3], y0 = base[n0*3+1], z0 = base[n0*3+2];
        float x1 = base[n1*3], y1 = base[n1*3+1], z1 = base[n1*3+2];
        sxyz[n0] = make_float4(x0, y0, z0, 0.f);
        sxyz[n1] = make_float4(x1, y1, z1, 0.f);
        px2[i] = pack2(-x0, -x1); py2[i] = pack2(-y0, -y1); pz2[i] = pack2(-z0, -z1);
        pd[2*i] = 1e10f; pd[2*i+1] = 1e10f;
    }
    __syncthreads();

    int far = 0;
    for (int s = 0; s < SS; s++) {
        float4 c = sxyz[far];
        if (t == 0) {
            float* o = out + ((size_t)b * SS + s) * 3;
            o[0] = c.x; o[1] = c.y; o[2] = c.z;
        }
        if (s == SS - 1) break;

        unsigned long long cxx = pack2(c.x, c.x), cyy = pack2(c.y, c.y), czz = pack2(c.z, c.z);
        float bv = -1.0f; int bi = 0;
#pragma unroll
        for (int i = 0; i < 4; i++) {
            unsigned long long dx = add2(cxx, px2[i]);   // c - p (== -(p-c), squared identical)
            unsigned long long dy = add2(cyy, py2[i]);
            unsigned long long dz = add2(czz, pz2[i]);
            unsigned long long ss2 = add2(add2(mul2(dx,dx), mul2(dy,dy)), mul2(dz,dz));
            float d0, d1; unpack2(d0, d1, ss2);
            float n0v = fminf(pd[2*i], d0); pd[2*i] = n0v;
            if (n0v > bv) { bv = n0v; bi = t + 1024*i; }
            float n1v = fminf(pd[2*i+1], d1); pd[2*i+1] = n1v;
            if (n1v > bv) { bv = n1v; bi = t + 1024*i + 512; }
        }
        unsigned vb = __float_as_uint(bv);                 // >=0: order-preserving
        unsigned mx = __reduce_max_sync(0xffffffffu, vb);
        unsigned cand = (vb == mx) ? (unsigned)bi : 0xffffffffu;
        unsigned mi = __reduce_min_sync(0xffffffffu, cand);

        int p = s & 1;
        if (lane == 0) { redv[p][w] = mx; redi[p][w] = mi; }
        __syncthreads();
        unsigned v2 = (lane < 16) ? redv[p][lane] : 0u;
        unsigned i2 = (lane < 16) ? redi[p][lane] : 0xffffffffu;
        unsigned m2 = __reduce_max_sync(0xffffffffu, v2);
        unsigned c2 = (v2 == m2) ? i2 : 0xffffffffu;
        far = (int)__reduce_min_sync(0xffffffffu, c2);
    }
}

// ---------------- fused kNN + gather ----------------
// grid (16, 8), 128 thr. 64 queries/block; each query scanned by 2 threads
// (2048 points each), merged by extract-min over the 32 candidates (set-exact).
// Distances clamped to >= 0: the metric can round to tiny negatives for the
// query's own point; the u64 (float_bits<<32|idx) merge compares UNSIGNED, so
// negatives would sort as largest and drop the nearest neighbor (R14's 8e-2 bug).
__global__ void knn_kernel(const float* __restrict__ xyz,
                           const float* __restrict__ newxyz,
                           const float* __restrict__ pts) {
    extern __shared__ unsigned char smraw[];
    float4* tile  = (float4*)smraw;                 // [4096] 65536B
    float*  sdist = (float*)(tile + NN);            // [16][128] 8192B
    int*    sidx  = (int*)(sdist + 16 * 128);       // [16][128] 8192B
    int*    midx  = (int*)(sidx + 16 * 128);        // [64*16]   4096B

    int b = blockIdx.y;
    int qc = blockIdx.x;
    int t = threadIdx.x;
    const float* base = xyz + (size_t)b * NN * 3;
#pragma unroll 4
    for (int i = 0; i < NN / 128; i++) {
        int n = t + i * 128;
        float x = base[n*3], y = base[n*3+1], z = base[n*3+2];
        tile[n] = make_float4(x, y, z, 0.5f*(x*x + y*y + z*z));
    }
    int q = qc * 64 + (t & 63);
    int jbase = (t >> 6) * 2048;
    const float* qp = newxyz + ((size_t)b * SS + q) * 3;
    float qx = qp[0], qy = qp[1], qz = qp[2];
    float qh = 0.5f*(qx*qx + qy*qy + qz*qz);
    float nqx = -qx, nqy = -qy, nqz = -qz;

#pragma unroll
    for (int sl = 0; sl < KNB; sl++) { sdist[sl*128+t] = 1e30f; sidx[sl*128+t] = 0; }
    __syncthreads();

    float maxv = 1e30f; int maxslot = 0;
    for (int jj = 0; jj < 2048; jj++) {
        int j = jbase + jj;
        float4 p = tile[j];
        float m = fmaf(nqx, p.x, fmaf(nqy, p.y, fmaf(nqz, p.z, qh + p.w)));
        m = fmaxf(m, 0.0f);                       // CRITICAL: keep keys non-negative
        if (m < maxv) {
            sdist[maxslot*128+t] = m;
            sidx [maxslot*128+t] = j;
            float mv = -1e30f; int ms = 0;
#pragma unroll
            for (int sl = 0; sl < KNB; sl++) {
                float d = sdist[sl*128+t];
                if (d > mv) { mv = d; ms = sl; }
            }
            maxv = mv; maxslot = ms;
        }
    }
    __syncthreads();

    // merge: thread t<64 selects 16 smallest of its query's 32 candidates
    if (t < 64) {
        unsigned long long key[32];
#pragma unroll
        for (int sl = 0; sl < KNB; sl++) {
            key[sl]      = ((unsigned long long)__float_as_uint(sdist[sl*128 + t])      << 32) | (unsigned)sidx[sl*128 + t];
            key[sl + 16] = ((unsigned long long)__float_as_uint(sdist[sl*128 + t + 64]) << 32) | (unsigned)sidx[sl*128 + t + 64];
        }
#pragma unroll
        for (int o = 0; o < KNB; o++) {
            unsigned long long mn = key[0]; int mj = 0;
#pragma unroll
            for (int j2 = 1; j2 < 32; j2++)
                if (key[j2] < mn) { mn = key[j2]; mj = j2; }
            midx[t * 16 + o] = (int)(mn & 0xffffffffu);
            key[mj] = 0xffffffffffffffffULL;
        }
    }
    __syncthreads();

    // gather: 1024 rows x 18 float4
    size_t bs0 = (size_t)b * SS + (size_t)qc * 64;
    for (int i = t; i < 1024 * 18; i += 128) {
        int c4 = i % 18;
        int r = i / 18;                       // qq = r>>4, slot = r&15
        int n = midx[r];
        size_t bs = bs0 + (r >> 4);
        size_t row = bs * 16 + (r & 15);
        float4 v;
        if (c4 < 16) {
            v = ((const float4*)(pts + ((size_t)b * NN + n) * 64))[c4];
        } else if (c4 == 16) {
            float4 p = tile[n];
            const float* qr = newxyz + bs * 3;
            v = make_float4(p.x - qr[0], p.y - qr[1], p.z - qr[2], 0.f);
        } else {
            v = make_float4(0.f, 0.f, 0.f, 0.f);
        }
        ((float4*)(g_X + row * XLD))[c4] = v;
    }
}

// ---------------- HMMA GEMM: C[128 x <=136] = act(A) @ W (bias dropped: BN absorbs it) ----------------
// smem: sSc[136]@0 | sSh[136]@576 | sSum[136]@1152 | sSq[136]@1728 | AH@2752 ...
template<bool USEBN>
__global__ __launch_bounds__(256) void tgemm_kernel(
    const float* __restrict__ A, int lda, int P, int ksteps,
    const __nv_bfloat16* __restrict__ BHg, const __nv_bfloat16* __restrict__ BLg,
    const float* __restrict__ gamma, const float* __restrict__ beta, int inlayer,
    float* __restrict__ C, int ldc, int outlayer)
{
    extern __shared__ char smc[];
    float* sSc   = (float*)smc;
    float* sSh   = (float*)(smc + 576);
    float* sSum  = (float*)(smc + 1152);
    float* sSq   = (float*)(smc + 1728);
    char* AH = smc + 2752;
    const int asz = 128 * P * 2;
    const int bsz = 136 * P * 2;
    char* AL = AH + asz;
    char* BHs = AL + asz;
    char* BLs = BHs + bsz;

    int t = threadIdx.x;

    if (t < 136) {
        sSum[t] = 0.f; sSq[t] = 0.f;
        if (USEBN) {
            float scv = 0.f, shv = 0.f;
            if (t < 134) {
                const float inv = 1.0f / (float)MROWS;
                float m = g_sum[inlayer][t] * inv;
                float v = g_sq [inlayer][t] * inv - m * m;
                scv = gamma[t] * rsqrtf(v + 1e-5f);
                shv = beta[t] - m * scv;
            }
            sSc[t] = scv; sSh[t] = shv;
        }
    }
    {
        int n16 = bsz >> 4;
        const float4* bh4 = (const float4*)BHg;
        const float4* bl4 = (const float4*)BLg;
        for (int i = t; i < n16; i += 256) {
            ((float4*)BHs)[i] = bh4[i];
            ((float4*)BLs)[i] = bl4[i];
        }
    }
    __syncthreads();

    // stage A: row = t/2, k-half = t&1; bn+relu fused; bf16 hi/lo split
    {
        int row = t >> 1;
        int halfbase = (t & 1) * (P >> 1);
        const float* arow = A + ((size_t)blockIdx.x * 128 + row) * lda;
        int nf4 = P >> 3;
        for (int i = 0; i < nf4; i++) {
            int k = halfbase + i * 4;
            float4 v = make_float4(0.f, 0.f, 0.f, 0.f);
            if (k < lda) {
                v = *(const float4*)(arow + k);
                if (USEBN) {
                    v.x = fmaxf(fmaf(v.x, sSc[k+0], sSh[k+0]), 0.f);
                    v.y = fmaxf(fmaf(v.y, sSc[k+1], sSh[k+1]), 0.f);
                    v.z = fmaxf(fmaf(v.z, sSc[k+2], sSh[k+2]), 0.f);
                    v.w = fmaxf(fmaf(v.w, sSc[k+3], sSh[k+3]), 0.f);
                }
            }
            __nv_bfloat162 h01 = __floats2bfloat162_rn(v.x, v.y);
            __nv_bfloat162 h23 = __floats2bfloat162_rn(v.z, v.w);
            __nv_bfloat162 l01 = __floats2bfloat162_rn(v.x - __bfloat162float(h01.x),
                                                       v.y - __bfloat162float(h01.y));
            __nv_bfloat162 l23 = __floats2bfloat162_rn(v.z - __bfloat162float(h23.x),
                                                       v.w - __bfloat162float(h23.y));
            size_t o = ((size_t)row * P + k) * 2;
            *(__nv_bfloat162*)(AH + o)     = h01;
            *(__nv_bfloat162*)(AH + o + 4) = h23;
            *(__nv_bfloat162*)(AL + o)     = l01;
            *(__nv_bfloat162*)(AL + o + 4) = l23;
        }
    }
    __syncthreads();

    // ---- MMA mainloop ----
    uint32_t sb = smem_u32(smc);
    uint32_t aHb = sb + 2752;
    uint32_t aLb = aHb + asz;
    uint32_t bHb = aLb + asz;
    uint32_t bLb = bHb + bsz;

    int wid = t >> 5, lane = t & 31;
    int g = lane >> 2, tg = lane & 3;
    int mg = wid & 3, ng = wid >> 2;
    int nbase = ng * 72;
    int ntiles = ng ? 8 : 9;
    uint32_t P2 = (uint32_t)P * 2;

    float acc[2][9][4];
#pragma unroll
    for (int mt = 0; mt < 2; mt++)
#pragma unroll
        for (int nt = 0; nt < 9; nt++)
#pragma unroll
            for (int i = 0; i < 4; i++) acc[mt][nt][i] = 0.f;

    for (int ks = 0; ks < ksteps; ks++) {
        uint32_t kboff = (uint32_t)(ks * 16 + tg * 2) * 2;
        uint32_t ah[2][4], al[2][4];
#pragma unroll
        for (int mt = 0; mt < 2; mt++) {
            uint32_t r0 = (uint32_t)(mg * 32 + mt * 16 + g);
            uint32_t b0 = r0 * P2 + kboff;
            uint32_t b1 = b0 + 8 * P2;
            ah[mt][0] = lds32(aHb + b0);      ah[mt][1] = lds32(aHb + b1);
            ah[mt][2] = lds32(aHb + b0 + 16); ah[mt][3] = lds32(aHb + b1 + 16);
            al[mt][0] = lds32(aLb + b0);      al[mt][1] = lds32(aLb + b1);
            al[mt][2] = lds32(aLb + b0 + 16); al[mt][3] = lds32(aLb + b1 + 16);
        }
#pragma unroll
        for (int nt = 0; nt < 9; nt++) {
            if (nt >= ntiles) break;
            uint32_t n0 = (uint32_t)(nbase + nt * 8 + g);
            uint32_t bb = n0 * P2 + kboff;
            uint32_t bh0 = lds32(bHb + bb), bh1 = lds32(bHb + bb + 16);
            uint32_t bl0 = lds32(bLb + bb), bl1 = lds32(bLb + bb + 16);
#pragma unroll
            for (int mt = 0; mt < 2; mt++) {
                mma_bf16(acc[mt][nt], ah[mt], bh0, bh1);
                mma_bf16(acc[mt][nt], ah[mt], bl0, bl1);
                mma_bf16(acc[mt][nt], al[mt], bh0, bh1);
            }
        }
    }

    // ---- epilogue: store + column stats (no bias: BN absorbs it) ----
    size_t rg0 = (size_t)blockIdx.x * 128 + mg * 32 + g;
#pragma unroll
    for (int nt = 0; nt < 9; nt++) {
        if (nt >= ntiles) break;
        int cb = nbase + nt * 8;
        int c0 = cb + tg * 2;
        float s0 = 0.f, s1 = 0.f, q0 = 0.f, q1 = 0.f;
#pragma unroll
        for (int mt = 0; mt < 2; mt++) {
            float* cc = acc[mt][nt];
            float v0 = cc[0], v1 = cc[1], v2 = cc[2], v3 = cc[3];
            if (cb < ldc) {
                size_t r0 = rg0 + mt * 16;
                *(float2*)(C + r0 * ldc + c0) = make_float2(v0, v1);
                *(float2*)(C + (r0 + 8) * ldc + c0) = make_float2(v2, v3);
            }
            s0 += v0 + v2; s1 += v1 + v3;
            q0 += v0 * v0 + v2 * v2; q1 += v1 * v1 + v3 * v3;
        }
#pragma unroll
        for (int off = 16; off >= 4; off >>= 1) {
            s0 += __shfl_down_sync(0xffffffffu, s0, off);
            s1 += __shfl_down_sync(0xffffffffu, s1, off);
            q0 += __shfl_down_sync(0xffffffffu, q0, off);
            q1 += __shfl_down_sync(0xffffffffu, q1, off);
        }
        if (lane < 4) {
            atomicAdd(&sSum[c0], s0); atomicAdd(&sSum[c0 + 1], s1);
            atomicAdd(&sSq [c0], q0); atomicAdd(&sSq [c0 + 1], q1);
        }
    }
    __syncthreads();
    if (t < 136) {
        atomicAdd(&g_sum[outlayer][t], sSum[t]);
        atomicAdd(&g_sq [outlayer][t], sSq[t]);
    }
}

// ---------------- final: relu(bn3(H3)+bnsc(SC)), max over K ----------------
__global__ void final_kernel(const float* __restrict__ g3, const float* __restrict__ b3,
                             const float* __restrict__ gsc, const float* __restrict__ bsc,
                             float* __restrict__ out) {
    int c = threadIdx.x;
    size_t bs = blockIdx.x;
    const float inv = 1.0f / (float)MROWS;
    float m = g_sum[2][c] * inv;
    float v = g_sq[2][c] * inv - m * m;
    float s3 = g3[c] * rsqrtf(v + 1e-5f);
    float h3 = b3[c] - m * s3;
    m = g_sum[3][c] * inv;
    v = g_sq[3][c] * inv - m * m;
    float ssc = gsc[c] * rsqrtf(v + 1e-5f);
    float hsc = bsc[c] - m * ssc;

    float mx = 0.0f;
    size_t base = bs * KNB;
#pragma unroll
    for (int kk = 0; kk < KNB; kk++) {
        float a  = fmaf(g_H3[(base + kk) * CO + c], s3, h3);
        float b2 = fmaf(g_SC[(base + kk) * CO + c], ssc, hsc);
        mx = fmaxf(mx, fmaxf(a + b2, 0.f));
    }
    out[24576 + bs * CO + c] = mx;
}

// ---------------- launch ----------------
extern "C" void kernel_launch(void* const* d_in, const int* in_sizes, int n_in,
                              void* d_out, int out_size) {
    const float* xyz   = (const float*)d_in[0];
    const float* pts   = (const float*)d_in[1];
    const float* fc1_w = (const float*)d_in[2];
    const float* bn1_g = (const float*)d_in[4];
    const float* bn1_b = (const float*)d_in[5];
    const float* fc2_w = (const float*)d_in[6];
    const float* bn2_g = (const float*)d_in[8];
    const float* bn2_b = (const float*)d_in[9];
    const float* fc3_w = (const float*)d_in[10];
    const float* bn3_g = (const float*)d_in[12];
    const float* bn3_b = (const float*)d_in[13];
    const float* sc_w  = (const float*)d_in[14];
    const float* scbn_g = (const float*)d_in[16];
    const float* scbn_b = (const float*)d_in[17];
    float* out = (float*)d_out;

    void *pX, *pH1, *pH2, *pH3, *pSC, *pBH, *pBL;
    cudaGetSymbolAddress(&pX,  g_X);
    cudaGetSymbolAddress(&pH1, g_H1);
    cudaGetSymbolAddress(&pH2, g_H2);
    cudaGetSymbolAddress(&pH3, g_H3);
    cudaGetSymbolAddress(&pSC, g_SC);
    cudaGetSymbolAddress(&pBH, g_BimgHi);
    cudaGetSymbolAddress(&pBL, g_BimgLo);
    float* X  = (float*)pX;
    float* H1 = (float*)pH1;
    float* H2 = (float*)pH2;
    float* H3 = (float*)pH3;
    float* SC = (float*)pSC;
    __nv_bfloat16* BH = (__nv_bfloat16*)pBH;
    __nv_bfloat16* BL = (__nv_bfloat16*)pBL;

    const int fps_smem = NN * 16;                          // 65536
    const int knn_smem = NN * 16 + 16*128*8 + 64*16*4;     // 86016
    const int sm88  = 2752 + 88  * 1056;   // 95680
    const int sm152 = 2752 + 152 * 1056;   // 163264

    cudaFuncSetAttribute(fps_kernel, cudaFuncAttributeMaxDynamicSharedMemorySize, fps_smem);
    cudaFuncSetAttribute(knn_kernel, cudaFuncAttributeMaxDynamicSharedMemorySize, knn_smem);
    cudaFuncSetAttribute(tgemm_kernel<false>, cudaFuncAttributeMaxDynamicSharedMemorySize, sm152);
    cudaFuncSetAttribute(tgemm_kernel<true>,  cudaFuncAttributeMaxDynamicSharedMemorySize, sm152);

    prep_kernel<<<255, 256>>>(fc1_w, sc_w, fc2_w, fc3_w);
    fps_kernel<<<BB, 512, fps_smem>>>(xyz, out);
    knn_kernel<<<dim3(16, BB), 128, knn_smem>>>(xyz, out, pts);

    // L1: H1 = X @ fc1_w   -> stats[0]
    tgemm_kernel<false><<<MROWS / 128, 256, sm88>>>(
        X, XLD, 88, 5, BH + 0, BL + 0, nullptr, nullptr, 0, H1, HLD, 0);
    // SC: SC = X @ sc_w    -> stats[3]
    tgemm_kernel<false><<<MROWS / 128, 256, sm88>>>(
        X, XLD, 88, 5, BH + 11968, BL + 11968, nullptr, nullptr, 0, SC, CO, 3);
    // L2: H2 = relu(bn1(H1)) @ fc2_w  -> stats[1]
    tgemm_kernel<true><<<MROWS / 128, 256, sm152>>>(
        H1, HLD, 152, 9, BH + 23936, BL + 23936, bn1_g, bn1_b, 0, H2, HLD, 1);
    // L3: H3 = relu(bn2(H2)) @ fc3_w  -> stats[2]
    tgemm_kernel<true><<<MROWS / 128, 256, sm152>>>(
        H2, HLD, 152, 9, BH + 44608, BL + 44608, bn2_g, bn2_b, 1, H3, CO, 2);

    final_kernel<<<BB * SS, 128>>>(bn3_g, bn3_b, scbn_g, scbn_b, out);
}